// round 3
// baseline (speedup 1.0000x reference)
#include <cuda_runtime.h>
#include <math.h>

// Problem constants
static const int CN = 32;    // batch
static const int CL = 512;   // nodes
static const int CP = 256;   // hyperedges
static const int CH = 8;     // heads
static const int CE = 128;   // emb per head
static const int CD = 1024;  // d_model

// -------- scratch (device globals; no allocation allowed) --------
__device__ __align__(16) float g_xh   [CN*CH*CL*CE];   // (n,h,l,e) post linear1
__device__ __align__(16) float g_he0  [CN*CH*CP*CE];   // gelu(edge aggregation)
__device__ __align__(16) float g_he   [CN*CH*CP*CE];   // hyper_edge (post linear3)
__device__ __align__(16) float g_maskT[CN*CP*CL];      // transposed incidence
__device__ __align__(16) float g_xv   [CN*CH*CL];
__device__ __align__(16) float g_an   [CN*CH*CL];      // a_node
__device__ __align__(16) float g_sp   [CN*CH*CL];      // softmax_h(xv) - 1/8
__device__ __align__(16) float g_ae   [CN*CH*CP];      // a_edge
__device__ __align__(16) float g_xhsum[CN*CH*CE];      // sum over l of xh
__device__ __align__(16) float g_hesum[CN*CH*CE];      // sum over p of he

__device__ __forceinline__ float gelu1(float x) {
    return 0.5f * x * (1.0f + erff(x * 0.7071067811865476f));
}

// -------- mask transpose: (n,l,p) -> (n,p,l) --------
__global__ void __launch_bounds__(256) tmask_k(const float* __restrict__ m) {
    __shared__ float s[32][33];
    int n = blockIdx.z;
    int p0 = blockIdx.x * 32, l0 = blockIdx.y * 32;
    int tx = threadIdx.x, ty = threadIdx.y;   // (32, 8)
    #pragma unroll
    for (int j = 0; j < 32; j += 8)
        s[ty + j][tx] = m[(size_t)n * CL * CP + (size_t)(l0 + ty + j) * CP + p0 + tx];
    __syncthreads();
    #pragma unroll
    for (int j = 0; j < 32; j += 8)
        g_maskT[(size_t)n * CP * CL + (size_t)(p0 + ty + j) * CL + l0 + tx] = s[tx][ty + j];
}

// -------- GEMM: C = A(Mx128) @ B(128x128) + bias --------
// PERM=true:  A = x (rows ordered (n,l,h)), C = g_xh (layout (n,h,l,e))
// PERM=false: A = g_he0, C = g_he (row-linear)
template<bool PERM>
__global__ void __launch_bounds__(128) gemm_k(const float* __restrict__ A_ext,
                                              const float* __restrict__ B,
                                              const float* __restrict__ bias) {
    __shared__ float As[16 * 68];
    __shared__ float Bs[16 * 128];
    const float* A = PERM ? A_ext : g_he0;
    float* C = PERM ? g_xh : g_he;

    const int tid = threadIdx.x;
    const int m0 = blockIdx.x * 64;
    const int tx = tid & 15, ty = tid >> 4;

    float acc[8][8];
    #pragma unroll
    for (int i = 0; i < 8; i++)
        #pragma unroll
        for (int j = 0; j < 8; j++) acc[i][j] = 0.0f;

    for (int kt = 0; kt < 8; ++kt) {
        #pragma unroll
        for (int r = 0; r < 2; ++r) {
            int i = tid + r * 128;
            int m = i >> 2, k4 = i & 3;
            float4 a = *(const float4*)(A + (size_t)(m0 + m) * 128 + kt * 16 + k4 * 4);
            As[(k4 * 4 + 0) * 68 + m] = a.x;
            As[(k4 * 4 + 1) * 68 + m] = a.y;
            As[(k4 * 4 + 2) * 68 + m] = a.z;
            As[(k4 * 4 + 3) * 68 + m] = a.w;
        }
        #pragma unroll
        for (int r = 0; r < 4; ++r) {
            int i = tid + r * 128;
            int k = i >> 5, c4 = i & 31;
            *(float4*)&Bs[k * 128 + c4 * 4] =
                *(const float4*)(B + (size_t)(kt * 16 + k) * 128 + c4 * 4);
        }
        __syncthreads();
        #pragma unroll
        for (int k = 0; k < 16; ++k) {
            float4 a0 = *(const float4*)&As[k * 68 + ty * 8];
            float4 a1 = *(const float4*)&As[k * 68 + ty * 8 + 4];
            float4 b0 = *(const float4*)&Bs[k * 128 + tx * 8];
            float4 b1 = *(const float4*)&Bs[k * 128 + tx * 8 + 4];
            float av[8] = {a0.x, a0.y, a0.z, a0.w, a1.x, a1.y, a1.z, a1.w};
            float bv[8] = {b0.x, b0.y, b0.z, b0.w, b1.x, b1.y, b1.z, b1.w};
            #pragma unroll
            for (int i = 0; i < 8; i++)
                #pragma unroll
                for (int j = 0; j < 8; j++)
                    acc[i][j] = fmaf(av[i], bv[j], acc[i][j]);
        }
        __syncthreads();
    }

    float4 bb0 = *(const float4*)(bias + tx * 8);
    float4 bb1 = *(const float4*)(bias + tx * 8 + 4);
    float bb[8] = {bb0.x, bb0.y, bb0.z, bb0.w, bb1.x, bb1.y, bb1.z, bb1.w};

    #pragma unroll
    for (int i = 0; i < 8; ++i) {
        int row = m0 + ty * 8 + i;
        size_t off;
        if (PERM) {
            int n = row >> 12;          // 4096 rows per n (l*8+h)
            int rem = row & 4095;
            int l = rem >> 3, h = rem & 7;
            off = ((size_t)((n * 8 + h) * 512 + l)) * 128;
        } else {
            off = (size_t)row * 128;
        }
        float4 o0, o1;
        o0.x = acc[i][0] + bb[0]; o0.y = acc[i][1] + bb[1];
        o0.z = acc[i][2] + bb[2]; o0.w = acc[i][3] + bb[3];
        o1.x = acc[i][4] + bb[4]; o1.y = acc[i][5] + bb[5];
        o1.z = acc[i][6] + bb[6]; o1.w = acc[i][7] + bb[7];
        *(float4*)(C + off + tx * 8)     = o0;
        *(float4*)(C + off + tx * 8 + 4) = o1;
    }
}

// -------- row dots: per row r: g = gelu(in[r]); out = g . w --------
// MODE 0: in g_xh -> g_xv (.W2), g_an (.W4hi)   MODE 1: in g_he -> g_ae (.W4lo)
template<int MODE>
__global__ void __launch_bounds__(256) rowdot_k(const float* __restrict__ wA,
                                                const float* __restrict__ wB) {
    const float* in = (MODE == 0) ? g_xh : g_he;
    int warp = threadIdx.x >> 5, lane = threadIdx.x & 31;
    size_t r = (size_t)blockIdx.x * 8 + warp;
    float4 v = *(const float4*)(in + r * 128 + lane * 4);
    float gx = gelu1(v.x), gy = gelu1(v.y), gz = gelu1(v.z), gw = gelu1(v.w);
    float4 wa = *(const float4*)(wA + lane * 4);
    float s1 = gx * wa.x + gy * wa.y + gz * wa.z + gw * wa.w;
    float s2 = 0.0f;
    if (MODE == 0) {
        float4 wb = *(const float4*)(wB + lane * 4);
        s2 = gx * wb.x + gy * wb.y + gz * wb.z + gw * wb.w;
    }
    #pragma unroll
    for (int off = 16; off > 0; off >>= 1) {
        s1 += __shfl_down_sync(0xffffffffu, s1, off);
        if (MODE == 0) s2 += __shfl_down_sync(0xffffffffu, s2, off);
    }
    if (lane == 0) {
        if (MODE == 0) { g_xv[r] = s1; g_an[r] = s2; }
        else           { g_ae[r] = s1; }
    }
}

// -------- middle-dim sum: out[o,e] = sum_m in[o,m,e] --------
// MM=512: g_xh -> g_xhsum ; MM=256: g_he -> g_hesum
template<int MM>
__global__ void __launch_bounds__(512) midsum_k() {
    __shared__ float sm[4][128];
    const float* in = (MM == 512) ? g_xh : g_he;
    float* out = (MM == 512) ? g_xhsum : g_hesum;
    int o = blockIdx.x;
    int e = threadIdx.x & 127, c = threadIdx.x >> 7;
    const float* base = in + ((size_t)o * MM) * 128 + e;
    float s = 0.0f;
    for (int m = c * (MM / 4); m < (c + 1) * (MM / 4); ++m)
        s += base[(size_t)m * 128];
    sm[c][e] = s;
    __syncthreads();
    if (threadIdx.x < 128)
        out[(size_t)o * 128 + e] = sm[0][e] + sm[1][e] + sm[2][e] + sm[3][e];
}

// -------- 8-way head softmax of xv; store softmax - 1/8 --------
__global__ void __launch_bounds__(256) softmax8_k() {
    int g = blockIdx.x * 256 + threadIdx.x;   // 0..N*L-1
    int n = g >> 9, l = g & 511;
    size_t base = ((size_t)n * 8) * 512 + l;
    float v[8]; float m = -1e30f;
    #pragma unroll
    for (int h = 0; h < 8; h++) { v[h] = g_xv[base + (size_t)h * 512]; m = fmaxf(m, v[h]); }
    float s = 0.0f;
    #pragma unroll
    for (int h = 0; h < 8; h++) { v[h] = __expf(v[h] - m); s += v[h]; }
    float inv = 1.0f / s;
    #pragma unroll
    for (int h = 0; h < 8; h++) g_sp[base + (size_t)h * 512] = v[h] * inv - 0.125f;
}

// -------- node->edge aggregation: he0 = gelu(1/8*xh_sum + sum_{valid l}(s-1/8)*xh) --------
__global__ void __launch_bounds__(256) hyperedge_k() {
    __shared__ float smask[512];
    __shared__ int lst[512];
    __shared__ int scnt;
    int p = blockIdx.x, n = blockIdx.y;
    int tid = threadIdx.x;
    const float* mrow = g_maskT + ((size_t)(n * CP + p)) * CL;
    smask[tid] = mrow[tid];
    smask[tid + 256] = mrow[tid + 256];
    __syncthreads();
    if (tid < 32) {
        int c = 0;
        for (int s = 0; s < 16; ++s) {
            int l = s * 32 + tid;
            float v = smask[l];
            unsigned b = __ballot_sync(0xffffffffu, v != 0.0f);
            if (v != 0.0f) lst[c + __popc(b & ((1u << tid) - 1u))] = l;
            c += __popc(b);
        }
        if (tid == 0) scnt = c;
    }
    __syncthreads();
    int cnt = scnt;
    int h = tid >> 5, lane = tid & 31;
    const float* xh_nh = g_xh + ((size_t)(n * 8 + h) * 512) * 128 + lane * 4;
    const float* sp_nh = g_sp + (size_t)(n * 8 + h) * 512;
    float4 acc0 = {0, 0, 0, 0}, acc1 = {0, 0, 0, 0};
    int i = 0;
    for (; i + 1 < cnt; i += 2) {
        int l0 = lst[i], l1 = lst[i + 1];
        float w0 = __ldg(sp_nh + l0), w1 = __ldg(sp_nh + l1);
        float4 v0 = *(const float4*)(xh_nh + (size_t)l0 * 128);
        float4 v1 = *(const float4*)(xh_nh + (size_t)l1 * 128);
        acc0.x = fmaf(w0, v0.x, acc0.x); acc0.y = fmaf(w0, v0.y, acc0.y);
        acc0.z = fmaf(w0, v0.z, acc0.z); acc0.w = fmaf(w0, v0.w, acc0.w);
        acc1.x = fmaf(w1, v1.x, acc1.x); acc1.y = fmaf(w1, v1.y, acc1.y);
        acc1.z = fmaf(w1, v1.z, acc1.z); acc1.w = fmaf(w1, v1.w, acc1.w);
    }
    if (i < cnt) {
        int l0 = lst[i];
        float w0 = __ldg(sp_nh + l0);
        float4 v0 = *(const float4*)(xh_nh + (size_t)l0 * 128);
        acc0.x = fmaf(w0, v0.x, acc0.x); acc0.y = fmaf(w0, v0.y, acc0.y);
        acc0.z = fmaf(w0, v0.z, acc0.z); acc0.w = fmaf(w0, v0.w, acc0.w);
    }
    float4 sm4 = *(const float4*)(g_xhsum + (size_t)(n * 8 + h) * 128 + lane * 4);
    float4 r;
    r.x = gelu1(0.125f * sm4.x + acc0.x + acc1.x);
    r.y = gelu1(0.125f * sm4.y + acc0.y + acc1.y);
    r.z = gelu1(0.125f * sm4.z + acc0.z + acc1.z);
    r.w = gelu1(0.125f * sm4.w + acc0.w + acc1.w);
    *(float4*)(g_he0 + ((size_t)(n * 8 + h) * 256 + p) * 128 + lane * 4) = r;
}

// -------- edge->node: fused per-p head-softmax + aggregation + gelu + scatter --------
__global__ void __launch_bounds__(256) node_k(const float* __restrict__ x,
                                              const float* __restrict__ mask,
                                              float* __restrict__ out) {
    __shared__ float smask[256];
    __shared__ int plst[256];
    __shared__ int scnt;
    __shared__ float ae_s[8 * 256];
    __shared__ float ws[8 * 256];
    __shared__ float an_s[8];
    int l = blockIdx.x, n = blockIdx.y;
    int tid = threadIdx.x;
    size_t mbase = ((size_t)(n * CL) + l) * CP;
    smask[tid] = mask[mbase + tid];
    if (tid < 8) an_s[tid] = g_an[(size_t)(n * 8 + tid) * 512 + l];
    #pragma unroll
    for (int j = 0; j < 8; ++j)
        ae_s[j * 256 + tid] = g_ae[(size_t)(n * 8 + j) * 256 + tid];
    __syncthreads();
    if (tid < 32) {
        int c = 0;
        for (int s = 0; s < 8; ++s) {
            int p = s * 32 + tid;
            float v = smask[p];
            unsigned b = __ballot_sync(0xffffffffu, v != 0.0f);
            if (v != 0.0f) plst[c + __popc(b & ((1u << tid) - 1u))] = p;
            c += __popc(b);
        }
        if (tid == 0) scnt = c;
    }
    __syncthreads();
    int cnt = scnt;
    if (cnt == 0) {
        // node participates in no hyperedge: output = input row
        const float4* xr = (const float4*)(x + ((size_t)(n * CL) + l) * CD);
        ((float4*)(out + ((size_t)(n * CL) + l) * CD))[tid] = xr[tid];
        return;
    }
    if (tid < cnt) {
        int p = plst[tid];
        float u[8]; float m = -1e30f;
        #pragma unroll
        for (int h = 0; h < 8; h++) { u[h] = an_s[h] + ae_s[h * 256 + p]; m = fmaxf(m, u[h]); }
        float s = 0.0f;
        #pragma unroll
        for (int h = 0; h < 8; h++) { u[h] = __expf(u[h] - m); s += u[h]; }
        float inv = 1.0f / s;
        #pragma unroll
        for (int h = 0; h < 8; h++) ws[h * 256 + tid] = u[h] * inv - 0.125f;
    }
    __syncthreads();
    int h = tid >> 5, lane = tid & 31;
    const float* he_nh = g_he + ((size_t)(n * 8 + h) * 256) * 128 + lane * 4;
    float4 acc0 = {0, 0, 0, 0}, acc1 = {0, 0, 0, 0};
    int i = 0;
    for (; i + 1 < cnt; i += 2) {
        int p0 = plst[i], p1 = plst[i + 1];
        float w0 = ws[h * 256 + i], w1 = ws[h * 256 + i + 1];
        float4 v0 = *(const float4*)(he_nh + (size_t)p0 * 128);
        float4 v1 = *(const float4*)(he_nh + (size_t)p1 * 128);
        acc0.x = fmaf(w0, v0.x, acc0.x); acc0.y = fmaf(w0, v0.y, acc0.y);
        acc0.z = fmaf(w0, v0.z, acc0.z); acc0.w = fmaf(w0, v0.w, acc0.w);
        acc1.x = fmaf(w1, v1.x, acc1.x); acc1.y = fmaf(w1, v1.y, acc1.y);
        acc1.z = fmaf(w1, v1.z, acc1.z); acc1.w = fmaf(w1, v1.w, acc1.w);
    }
    if (i < cnt) {
        int p0 = plst[i];
        float w0 = ws[h * 256 + i];
        float4 v0 = *(const float4*)(he_nh + (size_t)p0 * 128);
        acc0.x = fmaf(w0, v0.x, acc0.x); acc0.y = fmaf(w0, v0.y, acc0.y);
        acc0.z = fmaf(w0, v0.z, acc0.z); acc0.w = fmaf(w0, v0.w, acc0.w);
    }
    float4 hs = *(const float4*)(g_hesum + (size_t)(n * 8 + h) * 128 + lane * 4);
    float4 r;
    r.x = gelu1(acc0.x + acc1.x + 0.125f * hs.x);
    r.y = gelu1(acc0.y + acc1.y + 0.125f * hs.y);
    r.z = gelu1(acc0.z + acc1.z + 0.125f * hs.z);
    r.w = gelu1(acc0.w + acc1.w + 0.125f * hs.w);
    *(float4*)(out + ((size_t)(n * CL) + l) * CD + h * 128 + lane * 4) = r;
}

extern "C" void kernel_launch(void* const* d_in, const int* in_sizes, int n_in,
                              void* d_out, int out_size) {
    const float* x   = (const float*)d_in[0];
    const float* adj = (const float*)d_in[1];
    const float* W1  = (const float*)d_in[2];
    const float* b1  = (const float*)d_in[3];
    const float* W2  = (const float*)d_in[4];
    // b2 (d_in[5]) cancels inside the head softmax -> unused
    const float* W3  = (const float*)d_in[6];
    const float* b3  = (const float*)d_in[7];
    const float* W4  = (const float*)d_in[8];
    // b4 (d_in[9]) cancels inside the head softmax -> unused
    float* out = (float*)d_out;
    (void)in_sizes; (void)n_in; (void)out_size;

    tmask_k<<<dim3(CP / 32, CL / 32, CN), dim3(32, 8, 1)>>>(adj);
    gemm_k<true><<<(CN * CL * CH) / 64, 128>>>(x, W1, b1);            // -> g_xh
    rowdot_k<0><<<(CN * CH * CL) / 8, 256>>>(W2, W4 + CE);            // -> g_xv, g_an
    midsum_k<512><<<CN * CH, 512>>>();                                 // -> g_xhsum
    softmax8_k<<<(CN * CL) / 256, 256>>>();                            // -> g_sp
    hyperedge_k<<<dim3(CP, CN), 256>>>();                              // -> g_he0
    gemm_k<false><<<(CN * CH * CP) / 64, 128>>>(nullptr, W3, b3);      // -> g_he
    rowdot_k<1><<<(CN * CH * CP) / 8, 256>>>(W4, nullptr);             // -> g_ae
    midsum_k<256><<<CN * CH, 512>>>();                                 // -> g_hesum
    node_k<<<dim3(CL, CN), 256>>>(x, adj, out);                        // -> out
}

// round 4
// speedup vs baseline: 1.0327x; 1.0327x over previous
#include <cuda_runtime.h>
#include <math.h>
#include <stdint.h>

// Problem constants
static const int CN = 32;    // batch
static const int CL = 512;   // nodes
static const int CP = 256;   // hyperedges
static const int CH = 8;     // heads
static const int CE = 128;   // emb per head
static const int CD = 1024;  // d_model

// -------- scratch (device globals; no allocation allowed) --------
__device__ __align__(16) float    g_xh  [CN*CH*CL*CE];  // (n,h,l,e) post linear1
__device__ __align__(16) float    g_he0 [CN*CH*CP*CE];  // gelu(edge aggregation)
__device__ __align__(16) float    g_he  [CN*CH*CP*CE];  // hyper_edge (post linear3)
__device__ __align__(16) float    g_att2[CN*CH*CL*CP];  // dense node-attention (0.125 where masked)
__device__ __align__(16) unsigned g_mbits[CN*CP*16];    // mask bits: [n][p][l/32]
__device__ int   g_noedge[CN*CL];
__device__ float g_xv[CN*CH*CL];
__device__ float g_an[CN*CH*CL];   // a_node
__device__ float g_s [CN*CH*CL];   // softmax_h(xv)
__device__ float g_ae[CN*CH*CP];   // a_edge

__device__ __forceinline__ float gelu1(float x) {
    return 0.5f * x * (1.0f + erff(x * 0.7071067811865476f));
}
__device__ __forceinline__ unsigned f2tf(float x) {
    unsigned r; asm("cvt.rna.tf32.f32 %0, %1;" : "=r"(r) : "f"(x)); return r;
}
__device__ __forceinline__ void mma8(float* c, const unsigned* a, const unsigned* b) {
    asm volatile("mma.sync.aligned.m16n8k8.row.col.f32.tf32.tf32.f32 "
                 "{%0,%1,%2,%3},{%4,%5,%6,%7},{%8,%9},{%0,%1,%2,%3};"
                 : "+f"(c[0]), "+f"(c[1]), "+f"(c[2]), "+f"(c[3])
                 : "r"(a[0]), "r"(a[1]), "r"(a[2]), "r"(a[3]), "r"(b[0]), "r"(b[1]));
}

// -------- mask bit-pack: adj(n,l,p) -> g_mbits[n][p][l/32] --------
__global__ void __launch_bounds__(256) mbits_k(const float* __restrict__ adj) {
    __shared__ float sm[32 * 257];
    int l0 = blockIdx.x * 32, n = blockIdx.y;
    int t = threadIdx.x;   // = p
    for (int r = 0; r < 32; ++r)
        sm[r * 257 + t] = adj[((size_t)(n * CL) + l0 + r) * CP + t];
    __syncthreads();
    unsigned w = 0;
    #pragma unroll
    for (int j = 0; j < 32; ++j)
        if (sm[j * 257 + t] != 0.0f) w |= (1u << j);
    g_mbits[(n * CP + t) * 16 + (l0 >> 5)] = w;
}

// -------- row dots: per row r: g = gelu(in[r]); out = g . w --------
template<int MODE>
__global__ void __launch_bounds__(256) rowdot_k(const float* __restrict__ wA,
                                                const float* __restrict__ wB) {
    const float* in = (MODE == 0) ? g_xh : g_he;
    int warp = threadIdx.x >> 5, lane = threadIdx.x & 31;
    size_t r = (size_t)blockIdx.x * 8 + warp;
    float4 v = *(const float4*)(in + r * 128 + lane * 4);
    float gx = gelu1(v.x), gy = gelu1(v.y), gz = gelu1(v.z), gw = gelu1(v.w);
    float4 wa = *(const float4*)(wA + lane * 4);
    float s1 = gx * wa.x + gy * wa.y + gz * wa.z + gw * wa.w;
    float s2 = 0.0f;
    if (MODE == 0) {
        float4 wb = *(const float4*)(wB + lane * 4);
        s2 = gx * wb.x + gy * wb.y + gz * wb.z + gw * wb.w;
    }
    #pragma unroll
    for (int off = 16; off > 0; off >>= 1) {
        s1 += __shfl_down_sync(0xffffffffu, s1, off);
        if (MODE == 0) s2 += __shfl_down_sync(0xffffffffu, s2, off);
    }
    if (lane == 0) {
        if (MODE == 0) { g_xv[r] = s1; g_an[r] = s2; }
        else           { g_ae[r] = s1; }
    }
}

// -------- 8-way head softmax of xv --------
__global__ void __launch_bounds__(256) softmax8_k() {
    int g = blockIdx.x * 256 + threadIdx.x;
    int n = g >> 9, l = g & 511;
    size_t base = ((size_t)n * 8) * 512 + l;
    float v[8]; float m = -1e30f;
    #pragma unroll
    for (int h = 0; h < 8; h++) { v[h] = g_xv[base + (size_t)h * 512]; m = fmaxf(m, v[h]); }
    float s = 0.0f;
    #pragma unroll
    for (int h = 0; h < 8; h++) { v[h] = __expf(v[h] - m); s += v[h]; }
    float inv = 1.0f / s;
    #pragma unroll
    for (int h = 0; h < 8; h++) g_s[base + (size_t)h * 512] = v[h] * inv;
}

// -------- node-attention fill: dense (0.125 masked) + noedge flag --------
__global__ void __launch_bounds__(256) att2fill_k(const float* __restrict__ adj) {
    __shared__ float an_s[8];
    int l = blockIdx.x, n = blockIdx.y;
    int p = threadIdx.x;
    float mv = adj[((size_t)(n * CL) + l) * CP + p];
    int valid = (mv != 0.0f);
    if (p < 8) an_s[p] = g_an[(size_t)(n * 8 + p) * 512 + l];
    __syncthreads();
    float sm[8];
    if (valid) {
        float u[8]; float mx = -1e30f;
        #pragma unroll
        for (int h = 0; h < 8; h++) {
            u[h] = an_s[h] + g_ae[(size_t)(n * 8 + h) * 256 + p];
            mx = fmaxf(mx, u[h]);
        }
        float s = 0.0f;
        #pragma unroll
        for (int h = 0; h < 8; h++) { u[h] = __expf(u[h] - mx); s += u[h]; }
        float inv = 1.0f / s;
        #pragma unroll
        for (int h = 0; h < 8; h++) sm[h] = u[h] * inv;
    } else {
        #pragma unroll
        for (int h = 0; h < 8; h++) sm[h] = 0.125f;
    }
    #pragma unroll
    for (int h = 0; h < 8; h++)
        g_att2[(((size_t)(n * 8 + h)) * 512 + l) * 256 + p] = sm[h];
    int any = __syncthreads_or(valid);
    if (p == 0) g_noedge[n * CL + l] = !any;
}

// -------- unified tf32 MMA kernel: C(256x128) = A(256xK) * B(Kx128) --------
// MODE 0: A=x (M=131072, K=128), B=W1, +b1, PERM store -> g_xh
// MODE 1: A=g_he0 (M=65536, K=128), B=W3, +b3 -> g_he
// MODE 2: per (n,h): A=att1 on-the-fly (256p x 512l), B=g_xh(n,h), gelu -> g_he0
// MODE 3: per (n,h)x2: A=g_att2(n,h) (512l x 256p), B=g_he(n,h), gelu/scatter -> out
static const int SA = 20;    // As row stride (floats)
static const int SB = 136;   // Bs row stride (floats)

template<int MODE>
__global__ void __launch_bounds__(512) mma_k(const float* __restrict__ Aext,
                                             const float* __restrict__ Bext,
                                             const float* __restrict__ bias,
                                             const float* __restrict__ xin,
                                             float* __restrict__ outx) {
    __shared__ unsigned As[256 * SA];
    __shared__ unsigned Bs[16 * SB];
    __shared__ unsigned sS[512];   // MODE2: tf32 s-cache; MODE0/1: bias bits
    const int t = threadIdx.x;

    int nh = 0, m0 = 0, KT = 128, RS = 128;
    const float* Ag = Aext;
    const float* Bg = Bext;
    if (MODE == 0) { m0 = blockIdx.x * 256; }
    if (MODE == 1) { m0 = blockIdx.x * 256; Ag = g_he0; }
    if (MODE == 2) { nh = blockIdx.x; KT = 512; Bg = g_xh + (size_t)nh * 512 * 128; }
    if (MODE == 3) { nh = blockIdx.x >> 1; m0 = (blockIdx.x & 1) * 256; KT = 256; RS = 256;
                     Ag = g_att2 + (size_t)nh * 512 * 256;
                     Bg = g_he + (size_t)nh * 256 * 128; }

    if (MODE == 2) { sS[t] = f2tf(g_s[(size_t)nh * 512 + t]); }
    else if (MODE == 0 || MODE == 1) { if (t < 128) sS[t] = __float_as_uint(bias[t]); }

    const int lane = t & 31, wid = t >> 5;
    const int gq = lane >> 2, cq = lane & 3;
    const int wm = (wid & 3) * 64, wn = (wid >> 2) * 32;

    float acc[4][4][4];
    #pragma unroll
    for (int a = 0; a < 4; a++)
        #pragma unroll
        for (int b = 0; b < 4; b++)
            #pragma unroll
            for (int c = 0; c < 4; c++) acc[a][b][c] = 0.0f;

    for (int k0 = 0; k0 < KT; k0 += 16) {
        __syncthreads();
        // fill Bs (16 x 128)
        {
            int row = t >> 5, c4 = t & 31;
            float4 v = *(const float4*)(Bg + (size_t)(k0 + row) * 128 + c4 * 4);
            unsigned* d = &Bs[row * SB + c4 * 4];
            d[0] = f2tf(v.x); d[1] = f2tf(v.y); d[2] = f2tf(v.z); d[3] = f2tf(v.w);
        }
        // fill As (256 x 16)
        if (MODE == 2) {
            int p = t & 255, kh = (t >> 8) * 8;
            unsigned w = g_mbits[((nh >> 3) * 256 + p) * 16 + (k0 >> 5)];
            int sh = (k0 & 16);
            unsigned* d = &As[p * SA + kh];
            #pragma unroll
            for (int j = 0; j < 8; j++) {
                int k = kh + j;
                d[j] = ((w >> (sh + k)) & 1u) ? sS[k0 + k] : 0x3e000000u; // 0.125f
            }
        } else {
            #pragma unroll
            for (int rr = 0; rr < 2; rr++) {
                int i = t + 512 * rr;
                int row = i >> 2, c4 = i & 3;
                float4 v = *(const float4*)(Ag + (size_t)(m0 + row) * RS + k0 + c4 * 4);
                unsigned* d = &As[row * SA + c4 * 4];
                d[0] = f2tf(v.x); d[1] = f2tf(v.y); d[2] = f2tf(v.z); d[3] = f2tf(v.w);
            }
        }
        __syncthreads();
        #pragma unroll
        for (int ks = 0; ks < 16; ks += 8) {
            unsigned a[4][4], b[4][2];
            #pragma unroll
            for (int mi = 0; mi < 4; mi++) {
                int r0 = (wm + mi * 16 + gq) * SA + ks + cq;
                a[mi][0] = As[r0];
                a[mi][1] = As[r0 + 8 * SA];
                a[mi][2] = As[r0 + 4];
                a[mi][3] = As[r0 + 8 * SA + 4];
            }
            #pragma unroll
            for (int ni = 0; ni < 4; ni++) {
                int o = (ks + cq) * SB + wn + ni * 8 + gq;
                b[ni][0] = Bs[o];
                b[ni][1] = Bs[o + 4 * SB];
            }
            #pragma unroll
            for (int mi = 0; mi < 4; mi++)
                #pragma unroll
                for (int ni = 0; ni < 4; ni++)
                    mma8(acc[mi][ni], a[mi], b[ni]);
        }
    }

    // epilogue
    #pragma unroll
    for (int mi = 0; mi < 4; mi++) {
        #pragma unroll
        for (int half = 0; half < 2; half++) {
            int rl = wm + mi * 16 + gq + half * 8;
            size_t base = 0;
            int noe = 0;
            if (MODE == 0) {
                int rowg = m0 + rl;
                int n = rowg >> 12, rem = rowg & 4095;
                int l = rem >> 3, h = rem & 7;
                base = ((size_t)((n * 8 + h) * 512 + l)) * 128;
            } else if (MODE == 1) {
                base = (size_t)(m0 + rl) * 128;
            } else if (MODE == 2) {
                base = ((size_t)(nh * 256 + rl)) * 128;
            } else {
                int l = m0 + rl;
                int n = nh >> 3, h = nh & 7;
                noe = g_noedge[n * CL + l];
                base = ((size_t)(n * CL + l)) * 1024 + h * 128;
            }
            #pragma unroll
            for (int ni = 0; ni < 4; ni++) {
                int col = wn + ni * 8 + 2 * cq;
                float v0 = acc[mi][ni][half * 2 + 0];
                float v1 = acc[mi][ni][half * 2 + 1];
                if (MODE == 0) {
                    v0 += __uint_as_float(sS[col]);
                    v1 += __uint_as_float(sS[col + 1]);
                    *(float2*)(g_xh + base + col) = make_float2(v0, v1);
                } else if (MODE == 1) {
                    v0 += __uint_as_float(sS[col]);
                    v1 += __uint_as_float(sS[col + 1]);
                    *(float2*)(g_he + base + col) = make_float2(v0, v1);
                } else if (MODE == 2) {
                    *(float2*)(g_he0 + base + col) = make_float2(gelu1(v0), gelu1(v1));
                } else {
                    float2 r;
                    if (noe) {
                        r = *(const float2*)(xin + base + col);
                    } else {
                        r = make_float2(gelu1(v0), gelu1(v1));
                    }
                    *(float2*)(outx + base + col) = r;
                }
            }
        }
    }
}

extern "C" void kernel_launch(void* const* d_in, const int* in_sizes, int n_in,
                              void* d_out, int out_size) {
    const float* x   = (const float*)d_in[0];
    const float* adj = (const float*)d_in[1];
    const float* W1  = (const float*)d_in[2];
    const float* b1  = (const float*)d_in[3];
    const float* W2  = (const float*)d_in[4];
    // b2 (d_in[5]) cancels inside the head softmax -> unused
    const float* W3  = (const float*)d_in[6];
    const float* b3  = (const float*)d_in[7];
    const float* W4  = (const float*)d_in[8];
    // b4 (d_in[9]) cancels inside the head softmax -> unused
    float* out = (float*)d_out;
    (void)in_sizes; (void)n_in; (void)out_size;

    mbits_k<<<dim3(CL / 32, CN), 256>>>(adj);                          // -> g_mbits
    mma_k<0><<<(CN * CL * CH) / 256, 512>>>(x, W1, b1, nullptr, nullptr);      // -> g_xh
    rowdot_k<0><<<(CN * CH * CL) / 8, 256>>>(W2, W4 + CE);             // -> g_xv, g_an
    softmax8_k<<<(CN * CL) / 256, 256>>>();                             // -> g_s
    mma_k<2><<<CN * CH, 512>>>(nullptr, nullptr, nullptr, nullptr, nullptr);   // -> g_he0
    mma_k<1><<<(CN * CH * CP) / 256, 512>>>(nullptr, W3, b3, nullptr, nullptr); // -> g_he
    rowdot_k<1><<<(CN * CH * CP) / 8, 256>>>(W4, nullptr);             // -> g_ae
    att2fill_k<<<dim3(CL, CN), 256>>>(adj);                             // -> g_att2, g_noedge
    mma_k<3><<<CN * CH * 2, 512>>>(nullptr, nullptr, nullptr, x, out);  // -> out
}

// round 8
// speedup vs baseline: 1.2038x; 1.1657x over previous
#include <cuda_runtime.h>
#include <math.h>
#include <stdint.h>

// Problem constants
static const int CN = 32;    // batch
static const int CL = 512;   // nodes
static const int CP = 256;   // hyperedges
static const int CH = 8;     // heads
static const int CE = 128;   // emb per head
static const int CD = 1024;  // d_model

// -------- scratch (device globals; no allocation allowed) --------
__device__ __align__(16) float    g_xh  [CN*CH*CL*CE];  // (n,h,l,e) post linear1
__device__ __align__(16) float    g_he0 [CN*CH*CP*CE];  // gelu(edge aggregation)
__device__ __align__(16) float    g_he  [CN*CH*CP*CE];  // hyper_edge (post linear3)
__device__ __align__(16) float    g_att2[CN*CH*CL*CP];  // dense node-attention (0.125 where masked)
__device__ __align__(16) unsigned g_mbits[CN*CP*16];    // mask bits: [n][p][l/32]
__device__ int   g_noedge[CN*CL];
__device__ float g_an[CN*CH*CL];   // a_node
__device__ float g_s [CN*CH*CL];   // softmax_h(xv)
__device__ float g_ae[CN*CH*CP];   // a_edge

__device__ __forceinline__ float gelu1(float x) {
    return 0.5f * x * (1.0f + erff(x * 0.7071067811865476f));
}
__device__ __forceinline__ unsigned f2tf(float x) {
    unsigned r; asm("cvt.rna.tf32.f32 %0, %1;" : "=r"(r) : "f"(x)); return r;
}
__device__ __forceinline__ void mma8(float* c, const unsigned* a, const unsigned* b) {
    asm volatile("mma.sync.aligned.m16n8k8.row.col.f32.tf32.tf32.f32 "
                 "{%0,%1,%2,%3},{%4,%5,%6,%7},{%8,%9},{%0,%1,%2,%3};"
                 : "+f"(c[0]), "+f"(c[1]), "+f"(c[2]), "+f"(c[3])
                 : "r"(a[0]), "r"(a[1]), "r"(a[2]), "r"(a[3]), "r"(b[0]), "r"(b[1]));
}

// -------- mask bit-pack: adj(n,l,p) -> g_mbits[n][p][l/32] --------
__global__ void __launch_bounds__(256) mbits_k(const float* __restrict__ adj) {
    __shared__ float sm[32 * 257];
    int l0 = blockIdx.x * 32, n = blockIdx.y;
    int t = threadIdx.x;   // = p
    for (int r = 0; r < 32; ++r)
        sm[r * 257 + t] = adj[((size_t)(n * CL) + l0 + r) * CP + t];
    __syncthreads();
    unsigned w = 0;
    #pragma unroll
    for (int j = 0; j < 32; ++j)
        if (sm[j * 257 + t] != 0.0f) w |= (1u << j);
    g_mbits[(n * CP + t) * 16 + (l0 >> 5)] = w;
}

// -------- node-attention fill: dense (0.125 masked) + noedge flag --------
__global__ void __launch_bounds__(256) att2fill_k(const float* __restrict__ adj) {
    __shared__ float an_s[8];
    int l = blockIdx.x, n = blockIdx.y;
    int p = threadIdx.x;
    float mv = adj[((size_t)(n * CL) + l) * CP + p];
    int valid = (mv != 0.0f);
    if (p < 8) an_s[p] = g_an[(size_t)(n * 8 + p) * 512 + l];
    __syncthreads();
    float sm[8];
    if (valid) {
        float u[8]; float mx = -1e30f;
        #pragma unroll
        for (int h = 0; h < 8; h++) {
            u[h] = an_s[h] + g_ae[(size_t)(n * 8 + h) * 256 + p];
            mx = fmaxf(mx, u[h]);
        }
        float s = 0.0f;
        #pragma unroll
        for (int h = 0; h < 8; h++) { u[h] = __expf(u[h] - mx); s += u[h]; }
        float inv = 1.0f / s;
        #pragma unroll
        for (int h = 0; h < 8; h++) sm[h] = u[h] * inv;
    } else {
        #pragma unroll
        for (int h = 0; h < 8; h++) sm[h] = 0.125f;
    }
    #pragma unroll
    for (int h = 0; h < 8; h++)
        g_att2[(((size_t)(n * 8 + h)) * 512 + l) * 256 + p] = sm[h];
    int any = __syncthreads_or(valid);
    if (p == 0) g_noedge[n * CL + l] = !any;
}

// -------- unified tf32 MMA kernel, double-buffered --------
// MODE 0: A=x (M=131072,K=128), B=W1, +b1, PERM -> g_xh; fused gelu-dots(W2,W4hi)
//         + 8-head softmax -> g_s, g_an
// MODE 1: A=g_he0, B=W3, +b3 -> g_he; fused gelu-dot(W4lo) -> g_ae
// MODE 2: per (n,h): A=att1 on-the-fly from mbits/g_s, B=g_xh(n,h), gelu -> g_he0
// MODE 3: per (n,h)x2: A=g_att2(n,h), B=g_he(n,h), gelu/scatter -> out
static const int SA = 20;    // As row stride (u32)
static const int SB = 136;   // Bs row stride (u32)
static const int SMEM_WORDS = 2*256*SA + 2*16*SB + 512 + 128 + 128 + 1024 + 1024;
static const int SMEM_BYTES = SMEM_WORDS * 4;   // 69632

template<int MODE>
__global__ void __launch_bounds__(512) mma_k(const float* __restrict__ Aext,
                                             const float* __restrict__ Bext,
                                             const float* __restrict__ bias,
                                             const float* __restrict__ wA,
                                             const float* __restrict__ wB,
                                             const float* __restrict__ xin,
                                             float* __restrict__ outx) {
    extern __shared__ unsigned dyns[];
    unsigned* As  = dyns;                     // 2*256*SA
    unsigned* Bs  = As + 2 * 256 * SA;        // 2*16*SB
    unsigned* sS  = Bs + 2 * 16 * SB;         // 512: MODE2 tf32 s; MODE0/1 bias
    unsigned* sW2 = sS + 512;                 // 128
    unsigned* sW4 = sW2 + 128;                // 128
    float* sD1 = (float*)(sW4 + 128);         // 1024
    float* sD2 = sD1 + 1024;                  // 1024

    const int t = threadIdx.x;

    int nh = 0, m0 = 0, KT = 128, RS = 128;
    const float* Ag = Aext;
    const float* Bg = Bext;
    if (MODE == 0) { m0 = blockIdx.x * 256; }
    if (MODE == 1) { m0 = blockIdx.x * 256; Ag = g_he0; }
    if (MODE == 2) { nh = blockIdx.x; KT = 512; Bg = g_xh + (size_t)nh * 512 * 128; }
    if (MODE == 3) { nh = blockIdx.x >> 1; m0 = (blockIdx.x & 1) * 256; KT = 256; RS = 256;
                     Ag = g_att2 + (size_t)nh * 512 * 256;
                     Bg = g_he + (size_t)nh * 256 * 128; }

    if (MODE == 2) {
        sS[t] = f2tf(g_s[(size_t)nh * 512 + t]);
    } else if (MODE == 0 || MODE == 1) {
        if (t < 128) {
            sS[t] = __float_as_uint(bias[t]);
            sW2[t] = __float_as_uint(wA[t]);
            if (MODE == 0) sW4[t] = __float_as_uint(wB[t]);
        }
    }
    // sS is read cross-thread by storeT (MODE 2) below — must be visible first.
    __syncthreads();

    const int lane = t & 31, wid = t >> 5;
    const int gq = lane >> 2, cq = lane & 3;
    const int wm = (wid & 3) * 64, wn = (wid >> 2) * 32;

    float acc[4][4][4];
    #pragma unroll
    for (int a = 0; a < 4; a++)
        #pragma unroll
        for (int b = 0; b < 4; b++)
            #pragma unroll
            for (int c = 0; c < 4; c++) acc[a][b][c] = 0.0f;

    float4 pa0, pa1, pb;
    unsigned pmb = 0;

    auto loadT = [&](int k0) {
        int row = t >> 5, c4 = t & 31;
        pb = *(const float4*)(Bg + (size_t)(k0 + row) * 128 + c4 * 4);
        if (MODE == 2) {
            pmb = g_mbits[((nh >> 3) * 256 + (t & 255)) * 16 + (k0 >> 5)];
        } else {
            pa0 = *(const float4*)(Ag + (size_t)(m0 + (t >> 2)) * RS + k0 + (t & 3) * 4);
            int i1 = t + 512;
            pa1 = *(const float4*)(Ag + (size_t)(m0 + (i1 >> 2)) * RS + k0 + (i1 & 3) * 4);
        }
    };
    auto storeT = [&](int bf, int k0) {
        {
            int row = t >> 5, c4 = t & 31;
            unsigned* d = &Bs[bf * 16 * SB + row * SB + c4 * 4];
            d[0] = f2tf(pb.x); d[1] = f2tf(pb.y); d[2] = f2tf(pb.z); d[3] = f2tf(pb.w);
        }
        if (MODE == 2) {
            int p = t & 255, kh = (t >> 8) * 8, sh = (k0 & 16);
            unsigned* d = &As[bf * 256 * SA + p * SA + kh];
            #pragma unroll
            for (int j = 0; j < 8; j++) {
                int k = kh + j;
                d[j] = ((pmb >> (sh + k)) & 1u) ? sS[k0 + k] : 0x3e000000u; // 0.125f
            }
        } else {
            unsigned* d0 = &As[bf * 256 * SA + (t >> 2) * SA + (t & 3) * 4];
            d0[0] = f2tf(pa0.x); d0[1] = f2tf(pa0.y); d0[2] = f2tf(pa0.z); d0[3] = f2tf(pa0.w);
            int i1 = t + 512;
            unsigned* d1 = &As[bf * 256 * SA + (i1 >> 2) * SA + (i1 & 3) * 4];
            d1[0] = f2tf(pa1.x); d1[1] = f2tf(pa1.y); d1[2] = f2tf(pa1.z); d1[3] = f2tf(pa1.w);
        }
    };

    loadT(0);
    storeT(0, 0);
    __syncthreads();

    int bf = 0;
    for (int k0 = 0; k0 < KT; k0 += 16) {
        int nk = k0 + 16;
        if (nk < KT) loadT(nk);           // prefetch overlaps the MMAs below
        const unsigned* Ab = &As[bf * 256 * SA];
        const unsigned* Bb = &Bs[bf * 16 * SB];
        #pragma unroll
        for (int ks = 0; ks < 16; ks += 8) {
            unsigned a[4][4], b[4][2];
            #pragma unroll
            for (int mi = 0; mi < 4; mi++) {
                int r0 = (wm + mi * 16 + gq) * SA + ks + cq;
                a[mi][0] = Ab[r0];
                a[mi][1] = Ab[r0 + 8 * SA];
                a[mi][2] = Ab[r0 + 4];
                a[mi][3] = Ab[r0 + 8 * SA + 4];
            }
            #pragma unroll
            for (int ni = 0; ni < 4; ni++) {
                int o = (ks + cq) * SB + wn + ni * 8 + gq;
                b[ni][0] = Bb[o];
                b[ni][1] = Bb[o + 4 * SB];
            }
            #pragma unroll
            for (int mi = 0; mi < 4; mi++)
                #pragma unroll
                for (int ni = 0; ni < 4; ni++)
                    mma8(acc[mi][ni], a[mi], b[ni]);
        }
        if (nk < KT) {
            storeT(bf ^ 1, nk);
            __syncthreads();
        }
        bf ^= 1;
    }

    // ---------------- epilogue ----------------
    float dA[8], dB[8];
    #pragma unroll
    for (int i = 0; i < 8; i++) { dA[i] = 0.0f; dB[i] = 0.0f; }

    #pragma unroll
    for (int mi = 0; mi < 4; mi++) {
        #pragma unroll
        for (int half = 0; half < 2; half++) {
            int rl = wm + mi * 16 + gq + half * 8;
            int di = mi * 2 + half;
            size_t base = 0;
            int noe = 0;
            if (MODE == 0) {
                int rowg = m0 + rl;
                int n = rowg >> 12, rem = rowg & 4095;
                int l = rem >> 3, h = rem & 7;
                base = ((size_t)((n * 8 + h) * 512 + l)) * 128;
            } else if (MODE == 1) {
                base = (size_t)(m0 + rl) * 128;
            } else if (MODE == 2) {
                base = ((size_t)(nh * 256 + rl)) * 128;
            } else {
                int l = m0 + rl;
                int n = nh >> 3, h = nh & 7;
                noe = g_noedge[n * CL + l];
                base = ((size_t)(n * CL + l)) * 1024 + h * 128;
            }
            #pragma unroll
            for (int ni = 0; ni < 4; ni++) {
                int col = wn + ni * 8 + 2 * cq;
                float v0 = acc[mi][ni][half * 2 + 0];
                float v1 = acc[mi][ni][half * 2 + 1];
                if (MODE == 0 || MODE == 1) {
                    v0 += __uint_as_float(sS[col]);
                    v1 += __uint_as_float(sS[col + 1]);
                    float g0 = gelu1(v0), g1 = gelu1(v1);
                    dA[di] += g0 * __uint_as_float(sW2[col]) + g1 * __uint_as_float(sW2[col + 1]);
                    if (MODE == 0)
                        dB[di] += g0 * __uint_as_float(sW4[col]) + g1 * __uint_as_float(sW4[col + 1]);
                    float* dst = (MODE == 0) ? g_xh : g_he;
                    *(float2*)(dst + base + col) = make_float2(v0, v1);
                } else if (MODE == 2) {
                    *(float2*)(g_he0 + base + col) = make_float2(gelu1(v0), gelu1(v1));
                } else {
                    float2 r;
                    if (noe) r = *(const float2*)(xin + base + col);
                    else     r = make_float2(gelu1(v0), gelu1(v1));
                    *(float2*)(outx + base + col) = r;
                }
            }
        }
    }

    if (MODE == 0 || MODE == 1) {
        // reduce partial dots over the 4 cq lanes of each quad
        #pragma unroll
        for (int i = 0; i < 8; i++) {
            dA[i] += __shfl_xor_sync(0xffffffffu, dA[i], 1);
            dA[i] += __shfl_xor_sync(0xffffffffu, dA[i], 2);
            if (MODE == 0) {
                dB[i] += __shfl_xor_sync(0xffffffffu, dB[i], 1);
                dB[i] += __shfl_xor_sync(0xffffffffu, dB[i], 2);
            }
        }
        if (cq == 0) {
            #pragma unroll
            for (int i = 0; i < 8; i++) {
                int rl = wm + (i >> 1) * 16 + gq + 8 * (i & 1);
                sD1[(wid >> 2) * 256 + rl] = dA[i];
                if (MODE == 0) sD2[(wid >> 2) * 256 + rl] = dB[i];
            }
        }
        __syncthreads();
        if (t < 256) {   // warps 0..7 fully active: full-warp shfl is safe
            float d1 = sD1[t] + sD1[256 + t] + sD1[512 + t] + sD1[768 + t];
            if (MODE == 1) {
                g_ae[m0 + t] = d1;
            } else {
                float d2 = sD2[t] + sD2[256 + t] + sD2[512 + t] + sD2[768 + t];
                int rowg = m0 + t;
                int n = rowg >> 12, rem = rowg & 4095;
                int l = rem >> 3, h = rem & 7;
                g_an[(size_t)(n * 8 + h) * 512 + l] = d2;
                // 8-head softmax: rows t..t|7 share l (consecutive h)
                float mx = d1;
                mx = fmaxf(mx, __shfl_xor_sync(0xffffffffu, mx, 1));
                mx = fmaxf(mx, __shfl_xor_sync(0xffffffffu, mx, 2));
                mx = fmaxf(mx, __shfl_xor_sync(0xffffffffu, mx, 4));
                float e = __expf(d1 - mx);
                float se = e;
                se += __shfl_xor_sync(0xffffffffu, se, 1);
                se += __shfl_xor_sync(0xffffffffu, se, 2);
                se += __shfl_xor_sync(0xffffffffu, se, 4);
                g_s[(size_t)(n * 8 + h) * 512 + l] = e / se;
            }
        }
    }
}

extern "C" void kernel_launch(void* const* d_in, const int* in_sizes, int n_in,
                              void* d_out, int out_size) {
    const float* x   = (const float*)d_in[0];
    const float* adj = (const float*)d_in[1];
    const float* W1  = (const float*)d_in[2];
    const float* b1  = (const float*)d_in[3];
    const float* W2  = (const float*)d_in[4];
    // b2 (d_in[5]) cancels inside the head softmax -> unused
    const float* W3  = (const float*)d_in[6];
    const float* b3  = (const float*)d_in[7];
    const float* W4  = (const float*)d_in[8];
    // b4 (d_in[9]) cancels inside the head softmax -> unused
    float* out = (float*)d_out;
    (void)in_sizes; (void)n_in; (void)out_size;

    cudaFuncSetAttribute(mma_k<0>, cudaFuncAttributeMaxDynamicSharedMemorySize, SMEM_BYTES);
    cudaFuncSetAttribute(mma_k<1>, cudaFuncAttributeMaxDynamicSharedMemorySize, SMEM_BYTES);
    cudaFuncSetAttribute(mma_k<2>, cudaFuncAttributeMaxDynamicSharedMemorySize, SMEM_BYTES);
    cudaFuncSetAttribute(mma_k<3>, cudaFuncAttributeMaxDynamicSharedMemorySize, SMEM_BYTES);

    mbits_k<<<dim3(CL / 32, CN), 256>>>(adj);                              // -> g_mbits
    mma_k<0><<<(CN * CL * CH) / 256, 512, SMEM_BYTES>>>(x, W1, b1, W2, W4 + CE, nullptr, nullptr);
    mma_k<2><<<CN * CH, 512, SMEM_BYTES>>>(nullptr, nullptr, nullptr, nullptr, nullptr, nullptr, nullptr);
    mma_k<1><<<(CN * CH * CP) / 256, 512, SMEM_BYTES>>>(nullptr, W3, b3, W4, nullptr, nullptr, nullptr);
    att2fill_k<<<dim3(CL, CN), 256>>>(adj);                                // -> g_att2, g_noedge
    mma_k<3><<<CN * CH * 2, 512, SMEM_BYTES>>>(nullptr, nullptr, nullptr, nullptr, nullptr, x, out);
}

// round 9
// speedup vs baseline: 1.2667x; 1.0522x over previous
#include <cuda_runtime.h>
#include <math.h>
#include <stdint.h>

// Problem constants
static const int CN = 32;    // batch
static const int CL = 512;   // nodes
static const int CP = 256;   // hyperedges
static const int CH = 8;     // heads
static const int CE = 128;   // emb per head
static const int CD = 1024;  // d_model

// -------- scratch (device globals; no allocation allowed) --------
// NOTE: g_xh, g_he0, g_he, g_att2 hold tf32-rounded bit patterns (as float) —
// they are consumed only as MMA operands.
__device__ __align__(16) float    g_xh  [CN*CH*CL*CE];  // (n,h,l,e) post linear1
__device__ __align__(16) float    g_he0 [CN*CH*CP*CE];  // gelu(edge aggregation)
__device__ __align__(16) float    g_he  [CN*CH*CP*CE];  // hyper_edge (post linear3)
__device__ __align__(16) float    g_att2[CN*CH*CL*CP];  // dense node-attention
__device__ __align__(16) unsigned g_mbits[CN*CP*16];    // mask bits: [n][p][l/32]
__device__ int   g_noedge[CN*CL];
__device__ float g_an[CN*CH*CL];   // a_node
__device__ float g_s [CN*CH*CL];   // softmax_h(xv)
__device__ float g_ae[CN*CH*CP];   // a_edge

__device__ __forceinline__ float gelu1(float x) {
    return 0.5f * x * (1.0f + erff(x * 0.7071067811865476f));
}
__device__ __forceinline__ unsigned f2tf(float x) {
    unsigned r; asm("cvt.rna.tf32.f32 %0, %1;" : "=r"(r) : "f"(x)); return r;
}
__device__ __forceinline__ void mma8(float* c, const unsigned* a, const unsigned* b) {
    asm volatile("mma.sync.aligned.m16n8k8.row.col.f32.tf32.tf32.f32 "
                 "{%0,%1,%2,%3},{%4,%5,%6,%7},{%8,%9},{%0,%1,%2,%3};"
                 : "+f"(c[0]), "+f"(c[1]), "+f"(c[2]), "+f"(c[3])
                 : "r"(a[0]), "r"(a[1]), "r"(a[2]), "r"(a[3]), "r"(b[0]), "r"(b[1]));
}

// -------- mask bit-pack: adj(n,l,p) -> g_mbits[n][p][l/32] --------
__global__ void __launch_bounds__(256) mbits_k(const float* __restrict__ adj) {
    __shared__ float sm[32 * 257];
    int l0 = blockIdx.x * 32, n = blockIdx.y;
    int t = threadIdx.x;   // = p
    for (int r = 0; r < 32; ++r)
        sm[r * 257 + t] = adj[((size_t)(n * CL) + l0 + r) * CP + t];
    __syncthreads();
    unsigned w = 0;
    #pragma unroll
    for (int j = 0; j < 32; ++j)
        if (sm[j * 257 + t] != 0.0f) w |= (1u << j);
    g_mbits[(n * CP + t) * 16 + (l0 >> 5)] = w;
}

// -------- node-attention fill: dense tf32 (0.125 masked) + noedge flag --------
__global__ void __launch_bounds__(256) att2fill_k(const float* __restrict__ adj) {
    __shared__ float an_s[8];
    int l = blockIdx.x, n = blockIdx.y;
    int p = threadIdx.x;
    float mv = adj[((size_t)(n * CL) + l) * CP + p];
    int valid = (mv != 0.0f);
    if (p < 8) an_s[p] = g_an[(size_t)(n * 8 + p) * 512 + l];
    __syncthreads();
    unsigned sm[8];
    if (valid) {
        float u[8]; float mx = -1e30f;
        #pragma unroll
        for (int h = 0; h < 8; h++) {
            u[h] = an_s[h] + g_ae[(size_t)(n * 8 + h) * 256 + p];
            mx = fmaxf(mx, u[h]);
        }
        float s = 0.0f;
        #pragma unroll
        for (int h = 0; h < 8; h++) { u[h] = __expf(u[h] - mx); s += u[h]; }
        float inv = 1.0f / s;
        #pragma unroll
        for (int h = 0; h < 8; h++) sm[h] = f2tf(u[h] * inv);
    } else {
        #pragma unroll
        for (int h = 0; h < 8; h++) sm[h] = 0x3e000000u;   // tf32(0.125)
    }
    #pragma unroll
    for (int h = 0; h < 8; h++)
        g_att2[(((size_t)(n * 8 + h)) * 512 + l) * 256 + p] = __uint_as_float(sm[h]);
    int any = __syncthreads_or(valid);
    if (p == 0) g_noedge[n * CL + l] = !any;
}

// -------- unified tf32 MMA kernel, double-buffered, vectorized fragments ----
// MODE 0: A=x (M=131072,K=128), B=W1, +b1, PERM -> g_xh(tf32); fused gelu-dots
//         (W2,W4hi) + 8-head softmax -> g_s, g_an
// MODE 1: A=g_he0(raw tf32), B=W3, +b3 -> g_he(tf32); fused gelu-dot(W4lo) -> g_ae
// MODE 2: per (n,h): A=att1 on-the-fly from mbits/g_s, B=g_xh(raw), gelu-> g_he0(tf32)
// MODE 3: per (n,h)x2: A=g_att2(raw), B=g_he(raw), gelu/scatter -> out (fp32)
// A-tile layout: 32 blocks of 136 u32 per buffer; block (m16, ksc) holds 32
// 16B quads; quad at slot g*4+((c+g)&3) = fragment of thread (gq=g, cq=c):
// words [row g][k c], [row g+8][k c], [row g][k c+4], [row g+8][k c+4].
static const int ASZ = 32 * 136;   // per-buffer A words (4352)
static const int SB  = 136;        // Bs row stride (u32)
static const int BSZ = 16 * SB;    // per-buffer B words (2176)
static const int SMEM_WORDS = 2*ASZ + 2*BSZ + 512 + 128 + 128 + 1024 + 1024;
static const int SMEM_BYTES = SMEM_WORDS * 4;   // 63488

template<int MODE>
__global__ void __launch_bounds__(512) mma_k(const float* __restrict__ Aext,
                                             const float* __restrict__ Bext,
                                             const float* __restrict__ bias,
                                             const float* __restrict__ wA,
                                             const float* __restrict__ wB,
                                             const float* __restrict__ xin,
                                             float* __restrict__ outx) {
    extern __shared__ unsigned dyns[];
    unsigned* As  = dyns;                     // 2*ASZ
    unsigned* Bs  = As + 2 * ASZ;             // 2*BSZ
    unsigned* sS  = Bs + 2 * BSZ;             // 512: MODE2 tf32 s; MODE0/1 bias
    unsigned* sW2 = sS + 512;                 // 128
    unsigned* sW4 = sW2 + 128;                // 128
    float* sD1 = (float*)(sW4 + 128);         // 1024
    float* sD2 = sD1 + 1024;                  // 1024

    const bool CVA = (MODE == 0);
    const bool CVB = (MODE == 0 || MODE == 1);

    const int t = threadIdx.x;

    int nh = 0, m0 = 0, KT = 128, RS = 128;
    const float* Ag = Aext;
    const float* Bg = Bext;
    if (MODE == 0) { m0 = blockIdx.x * 256; }
    if (MODE == 1) { m0 = blockIdx.x * 256; Ag = g_he0; }
    if (MODE == 2) { nh = blockIdx.x; KT = 512; Bg = g_xh + (size_t)nh * 512 * 128; }
    if (MODE == 3) { nh = blockIdx.x >> 1; m0 = (blockIdx.x & 1) * 256; KT = 256; RS = 256;
                     Ag = g_att2 + (size_t)nh * 512 * 256;
                     Bg = g_he + (size_t)nh * 256 * 128; }

    if (MODE == 2) {
        sS[t] = f2tf(g_s[(size_t)nh * 512 + t]);
    } else if (MODE == 0 || MODE == 1) {
        if (t < 128) {
            sS[t] = __float_as_uint(bias[t]);
            sW2[t] = __float_as_uint(wA[t]);
            if (MODE == 0) sW4[t] = __float_as_uint(wB[t]);
        }
    }
    // sS is read cross-thread by storeT (MODE 2) below — must be visible first.
    __syncthreads();

    const int lane = t & 31, wid = t >> 5;
    const int gq = lane >> 2, cq = lane & 3;
    const int wm = (wid & 3) * 64, wn = (wid >> 2) * 32;

    float acc[4][4][4];
    #pragma unroll
    for (int a = 0; a < 4; a++)
        #pragma unroll
        for (int b = 0; b < 4; b++)
            #pragma unroll
            for (int c = 0; c < 4; c++) acc[a][b][c] = 0.0f;

    float4 pa0, pa1, pb;
    unsigned pmb = 0;

    auto loadT = [&](int k0) {
        int row = t >> 5, c4 = t & 31;
        pb = *(const float4*)(Bg + (size_t)(k0 + row) * 128 + c4 * 4);
        if (MODE == 2) {
            pmb = g_mbits[((nh >> 3) * 256 + (t & 255)) * 16 + (k0 >> 5)];
        } else {
            pa0 = *(const float4*)(Ag + (size_t)(m0 + (t >> 2)) * RS + k0 + (t & 3) * 4);
            int i1 = t + 512;
            pa1 = *(const float4*)(Ag + (size_t)(m0 + (i1 >> 2)) * RS + k0 + (i1 & 3) * 4);
        }
    };
    auto storeT = [&](int bf, int k0) {
        {
            int kk = t >> 5, c4 = t & 31;
            unsigned* d = &Bs[bf * BSZ + kk * SB + c4 * 4];
            if (CVB) { d[0]=f2tf(pb.x); d[1]=f2tf(pb.y); d[2]=f2tf(pb.z); d[3]=f2tf(pb.w); }
            else     { d[0]=__float_as_uint(pb.x); d[1]=__float_as_uint(pb.y);
                       d[2]=__float_as_uint(pb.z); d[3]=__float_as_uint(pb.w); }
        }
        if (MODE == 2) {
            int p = t & 255, kh = (t >> 8) * 8, sh = (k0 & 16);
            int m16 = p >> 4, r8 = (p >> 3) & 1, g8 = p & 7, rot = g8 & 3;
            int ksc = kh >> 3;
            unsigned* d = &As[bf * ASZ + (m16 * 2 + ksc) * 136 + g8 * 16 + r8];
            #pragma unroll
            for (int j = 0; j < 8; j++) {
                unsigned val = ((pmb >> (sh + kh + j)) & 1u) ? sS[k0 + kh + j]
                                                             : 0x3e000000u; // tf32(0.125)
                d[((( (j & 3) + rot) & 3) * 4) + 2 * (j >> 2)] = val;
            }
        } else {
            #pragma unroll
            for (int rr = 0; rr < 2; rr++) {
                int i = t + 512 * rr;
                float4 v = rr ? pa1 : pa0;
                int row = i >> 2, k0c = (i & 3) * 4;
                int m16 = row >> 4, r8 = (row >> 3) & 1, g8 = row & 7, rot = g8 & 3;
                int ksc = k0c >> 3, kh2 = (k0c >> 2) & 1;
                unsigned* d = &As[bf * ASZ + (m16 * 2 + ksc) * 136 + g8 * 16 + r8 + 2 * kh2];
                unsigned w0, w1, w2, w3;
                if (CVA) { w0=f2tf(v.x); w1=f2tf(v.y); w2=f2tf(v.z); w3=f2tf(v.w); }
                else     { w0=__float_as_uint(v.x); w1=__float_as_uint(v.y);
                           w2=__float_as_uint(v.z); w3=__float_as_uint(v.w); }
                d[((0 + rot) & 3) * 4] = w0;
                d[((1 + rot) & 3) * 4] = w1;
                d[((2 + rot) & 3) * 4] = w2;
                d[((3 + rot) & 3) * 4] = w3;
            }
        }
    };

    loadT(0);
    storeT(0, 0);
    __syncthreads();

    const int slotA = (gq * 4 + ((cq + gq) & 3)) * 4;
    const int m16w = wm >> 4;   // first 16-row group of this warp

    int bf = 0;
    for (int k0 = 0; k0 < KT; k0 += 16) {
        int nk = k0 + 16;
        if (nk < KT) loadT(nk);           // prefetch overlaps the MMAs below
        const unsigned* Ab = &As[bf * ASZ];
        const unsigned* Bb = &Bs[bf * BSZ];
        #pragma unroll
        for (int ksc = 0; ksc < 2; ksc++) {
            unsigned a[4][4], b[4][2];
            #pragma unroll
            for (int mi = 0; mi < 4; mi++) {
                uint4 v = *(const uint4*)&Ab[((m16w + mi) * 2 + ksc) * 136 + slotA];
                a[mi][0] = v.x; a[mi][1] = v.y; a[mi][2] = v.z; a[mi][3] = v.w;
            }
            #pragma unroll
            for (int ni = 0; ni < 4; ni++) {
                int o = (ksc * 8 + cq) * SB + wn + ni * 8 + gq;
                b[ni][0] = Bb[o];
                b[ni][1] = Bb[o + 4 * SB];
            }
            #pragma unroll
            for (int mi = 0; mi < 4; mi++)
                #pragma unroll
                for (int ni = 0; ni < 4; ni++)
                    mma8(acc[mi][ni], a[mi], b[ni]);
        }
        if (nk < KT) {
            storeT(bf ^ 1, nk);
            __syncthreads();
        }
        bf ^= 1;
    }

    // ---------------- epilogue ----------------
    float dA[8], dB[8];
    #pragma unroll
    for (int i = 0; i < 8; i++) { dA[i] = 0.0f; dB[i] = 0.0f; }

    #pragma unroll
    for (int mi = 0; mi < 4; mi++) {
        #pragma unroll
        for (int half = 0; half < 2; half++) {
            int rl = wm + mi * 16 + gq + half * 8;
            int di = mi * 2 + half;
            size_t base = 0;
            int noe = 0;
            if (MODE == 0) {
                int rowg = m0 + rl;
                int n = rowg >> 12, rem = rowg & 4095;
                int l = rem >> 3, h = rem & 7;
                base = ((size_t)((n * 8 + h) * 512 + l)) * 128;
            } else if (MODE == 1) {
                base = (size_t)(m0 + rl) * 128;
            } else if (MODE == 2) {
                base = ((size_t)(nh * 256 + rl)) * 128;
            } else {
                int l = m0 + rl;
                int n = nh >> 3, h = nh & 7;
                noe = g_noedge[n * CL + l];
                base = ((size_t)(n * CL + l)) * 1024 + h * 128;
            }
            #pragma unroll
            for (int ni = 0; ni < 4; ni++) {
                int col = wn + ni * 8 + 2 * cq;
                float v0 = acc[mi][ni][half * 2 + 0];
                float v1 = acc[mi][ni][half * 2 + 1];
                if (MODE == 0 || MODE == 1) {
                    v0 += __uint_as_float(sS[col]);
                    v1 += __uint_as_float(sS[col + 1]);
                    float g0 = gelu1(v0), g1 = gelu1(v1);
                    dA[di] += g0 * __uint_as_float(sW2[col]) + g1 * __uint_as_float(sW2[col + 1]);
                    if (MODE == 0)
                        dB[di] += g0 * __uint_as_float(sW4[col]) + g1 * __uint_as_float(sW4[col + 1]);
                    float* dst = (MODE == 0) ? g_xh : g_he;
                    // store tf32-rounded bits: consumed only as MMA operands
                    *(float2*)(dst + base + col) =
                        make_float2(__uint_as_float(f2tf(v0)), __uint_as_float(f2tf(v1)));
                } else if (MODE == 2) {
                    *(float2*)(g_he0 + base + col) =
                        make_float2(__uint_as_float(f2tf(gelu1(v0))),
                                    __uint_as_float(f2tf(gelu1(v1))));
                } else {
                    float2 r;
                    if (noe) r = *(const float2*)(xin + base + col);
                    else     r = make_float2(gelu1(v0), gelu1(v1));
                    *(float2*)(outx + base + col) = r;
                }
            }
        }
    }

    if (MODE == 0 || MODE == 1) {
        // reduce partial dots over the 4 cq lanes of each quad
        #pragma unroll
        for (int i = 0; i < 8; i++) {
            dA[i] += __shfl_xor_sync(0xffffffffu, dA[i], 1);
            dA[i] += __shfl_xor_sync(0xffffffffu, dA[i], 2);
            if (MODE == 0) {
                dB[i] += __shfl_xor_sync(0xffffffffu, dB[i], 1);
                dB[i] += __shfl_xor_sync(0xffffffffu, dB[i], 2);
            }
        }
        if (cq == 0) {
            #pragma unroll
            for (int i = 0; i < 8; i++) {
                int rl = wm + (i >> 1) * 16 + gq + 8 * (i & 1);
                sD1[(wid >> 2) * 256 + rl] = dA[i];
                if (MODE == 0) sD2[(wid >> 2) * 256 + rl] = dB[i];
            }
        }
        __syncthreads();
        if (t < 256) {   // warps 0..7 fully active: full-warp shfl is safe
            float d1 = sD1[t] + sD1[256 + t] + sD1[512 + t] + sD1[768 + t];
            if (MODE == 1) {
                g_ae[m0 + t] = d1;
            } else {
                float d2 = sD2[t] + sD2[256 + t] + sD2[512 + t] + sD2[768 + t];
                int rowg = m0 + t;
                int n = rowg >> 12, rem = rowg & 4095;
                int l = rem >> 3, h = rem & 7;
                g_an[(size_t)(n * 8 + h) * 512 + l] = d2;
                // 8-head softmax: rows t..t|7 share l (consecutive h)
                float mx = d1;
                mx = fmaxf(mx, __shfl_xor_sync(0xffffffffu, mx, 1));
                mx = fmaxf(mx, __shfl_xor_sync(0xffffffffu, mx, 2));
                mx = fmaxf(mx, __shfl_xor_sync(0xffffffffu, mx, 4));
                float e = __expf(d1 - mx);
                float se = e;
                se += __shfl_xor_sync(0xffffffffu, se, 1);
                se += __shfl_xor_sync(0xffffffffu, se, 2);
                se += __shfl_xor_sync(0xffffffffu, se, 4);
                g_s[(size_t)(n * 8 + h) * 512 + l] = e / se;
            }
        }
    }
}

extern "C" void kernel_launch(void* const* d_in, const int* in_sizes, int n_in,
                              void* d_out, int out_size) {
    const float* x   = (const float*)d_in[0];
    const float* adj = (const float*)d_in[1];
    const float* W1  = (const float*)d_in[2];
    const float* b1  = (const float*)d_in[3];
    const float* W2  = (const float*)d_in[4];
    // b2 (d_in[5]) cancels inside the head softmax -> unused
    const float* W3  = (const float*)d_in[6];
    const float* b3  = (const float*)d_in[7];
    const float* W4  = (const float*)d_in[8];
    // b4 (d_in[9]) cancels inside the head softmax -> unused
    float* out = (float*)d_out;
    (void)in_sizes; (void)n_in; (void)out_size;

    cudaFuncSetAttribute(mma_k<0>, cudaFuncAttributeMaxDynamicSharedMemorySize, SMEM_BYTES);
    cudaFuncSetAttribute(mma_k<1>, cudaFuncAttributeMaxDynamicSharedMemorySize, SMEM_BYTES);
    cudaFuncSetAttribute(mma_k<2>, cudaFuncAttributeMaxDynamicSharedMemorySize, SMEM_BYTES);
    cudaFuncSetAttribute(mma_k<3>, cudaFuncAttributeMaxDynamicSharedMemorySize, SMEM_BYTES);

    mbits_k<<<dim3(CL / 32, CN), 256>>>(adj);                              // -> g_mbits
    mma_k<0><<<(CN * CL * CH) / 256, 512, SMEM_BYTES>>>(x, W1, b1, W2, W4 + CE, nullptr, nullptr);
    mma_k<2><<<CN * CH, 512, SMEM_BYTES>>>(nullptr, nullptr, nullptr, nullptr, nullptr, nullptr, nullptr);
    mma_k<1><<<(CN * CH * CP) / 256, 512, SMEM_BYTES>>>(nullptr, W3, b3, W4, nullptr, nullptr, nullptr);
    att2fill_k<<<dim3(CL, CN), 256>>>(adj);                                // -> g_att2, g_noedge
    mma_k<3><<<CN * CH * 2, 512, SMEM_BYTES>>>(nullptr, nullptr, nullptr, nullptr, nullptr, x, out);
}

// round 10
// speedup vs baseline: 1.3877x; 1.0955x over previous
#include <cuda_runtime.h>
#include <math.h>
#include <stdint.h>

// Problem constants
static const int CN = 32;    // batch
static const int CL = 512;   // nodes
static const int CP = 256;   // hyperedges
static const int CH = 8;     // heads
static const int CE = 128;   // emb per head
static const int CD = 1024;  // d_model

// -------- scratch (device globals; no allocation allowed) --------
// g_xh, g_he0, g_he, g_att2 hold tf32-rounded bit patterns (as float) —
// they are consumed only as MMA operands.
__device__ __align__(16) float    g_xh  [CN*CH*CL*CE];
__device__ __align__(16) float    g_he0 [CN*CH*CP*CE];
__device__ __align__(16) float    g_he  [CN*CH*CP*CE];
__device__ __align__(16) float    g_att2[CN*CH*CL*CP];
__device__ __align__(16) unsigned g_mbits[CN*CP*16];    // [n][p][l/32]
__device__ int   g_noedge[CN*CL];
__device__ float g_an[CN*CH*CL];
__device__ float g_s [CN*CH*CL];
__device__ float g_ae[CN*CH*CP];

__device__ __forceinline__ float gelu1(float x) {
    return 0.5f * x * (1.0f + erff(x * 0.7071067811865476f));
}
__device__ __forceinline__ unsigned f2tf(float x) {
    unsigned r; asm("cvt.rna.tf32.f32 %0, %1;" : "=r"(r) : "f"(x)); return r;
}
__device__ __forceinline__ void mma8(float* c, const unsigned* a, const unsigned* b) {
    asm volatile("mma.sync.aligned.m16n8k8.row.col.f32.tf32.tf32.f32 "
                 "{%0,%1,%2,%3},{%4,%5,%6,%7},{%8,%9},{%0,%1,%2,%3};"
                 : "+f"(c[0]), "+f"(c[1]), "+f"(c[2]), "+f"(c[3])
                 : "r"(a[0]), "r"(a[1]), "r"(a[2]), "r"(a[3]), "r"(b[0]), "r"(b[1]));
}

// -------- mask bit-pack --------
__global__ void __launch_bounds__(256) mbits_k(const float* __restrict__ adj) {
    __shared__ float sm[32 * 257];
    int l0 = blockIdx.x * 32, n = blockIdx.y;
    int t = threadIdx.x;   // = p
    for (int r = 0; r < 32; ++r)
        sm[r * 257 + t] = adj[((size_t)(n * CL) + l0 + r) * CP + t];
    __syncthreads();
    unsigned w = 0;
    #pragma unroll
    for (int j = 0; j < 32; ++j)
        if (sm[j * 257 + t] != 0.0f) w |= (1u << j);
    g_mbits[(n * CP + t) * 16 + (l0 >> 5)] = w;
}

// -------- node-attention fill (tf32 bits) + noedge flag --------
__global__ void __launch_bounds__(256) att2fill_k(const float* __restrict__ adj) {
    __shared__ float an_s[8];
    int l = blockIdx.x, n = blockIdx.y;
    int p = threadIdx.x;
    float mv = adj[((size_t)(n * CL) + l) * CP + p];
    int valid = (mv != 0.0f);
    if (p < 8) an_s[p] = g_an[(size_t)(n * 8 + p) * 512 + l];
    __syncthreads();
    unsigned sm[8];
    if (valid) {
        float u[8]; float mx = -1e30f;
        #pragma unroll
        for (int h = 0; h < 8; h++) {
            u[h] = an_s[h] + g_ae[(size_t)(n * 8 + h) * 256 + p];
            mx = fmaxf(mx, u[h]);
        }
        float s = 0.0f;
        #pragma unroll
        for (int h = 0; h < 8; h++) { u[h] = __expf(u[h] - mx); s += u[h]; }
        float inv = 1.0f / s;
        #pragma unroll
        for (int h = 0; h < 8; h++) sm[h] = f2tf(u[h] * inv);
    } else {
        #pragma unroll
        for (int h = 0; h < 8; h++) sm[h] = 0x3e000000u;   // tf32(0.125)
    }
    #pragma unroll
    for (int h = 0; h < 8; h++)
        g_att2[(((size_t)(n * 8 + h)) * 512 + l) * 256 + p] = __uint_as_float(sm[h]);
    int any = __syncthreads_or(valid);
    if (p == 0) g_noedge[n * CL + l] = !any;
}

// -------- unified tf32 MMA kernel: 256 threads, M-tile 128, 2 CTAs/SM ------
// MODE 0: A=x, B=W1, +b1, PERM -> g_xh(tf32); fused gelu-dots + head softmax
// MODE 1: A=g_he0(raw), B=W3, +b3 -> g_he(tf32); fused gelu-dot -> g_ae
// MODE 2: per (n,h)x2: A=att1 from mbits/g_s, B=g_xh(raw), gelu -> g_he0(tf32)
// MODE 3: per (n,h)x4: A=g_att2(raw), B=g_he(raw), gelu/scatter -> out (fp32)
static const int ASZ = 16 * 136;   // 128 rows x 16 k, blocked
static const int SB  = 136;
static const int BSZ = 16 * SB;
static const int SMEM_WORDS = 2*ASZ + 2*BSZ + 512 + 128 + 128 + 512 + 512;
static const int SMEM_BYTES = SMEM_WORDS * 4;   // 41984

template<int MODE>
__global__ void __launch_bounds__(256, 2) mma_k(const float* __restrict__ Aext,
                                                const float* __restrict__ Bext,
                                                const float* __restrict__ bias,
                                                const float* __restrict__ wA,
                                                const float* __restrict__ wB,
                                                const float* __restrict__ xin,
                                                float* __restrict__ outx) {
    extern __shared__ unsigned dyns[];
    unsigned* As  = dyns;                     // 2*ASZ
    unsigned* Bs  = As + 2 * ASZ;             // 2*BSZ
    unsigned* sS  = Bs + 2 * BSZ;             // 512
    unsigned* sW2 = sS + 512;                 // 128
    unsigned* sW4 = sW2 + 128;                // 128
    float* sD1 = (float*)(sW4 + 128);         // 512
    float* sD2 = sD1 + 512;                   // 512

    const bool CVA = (MODE == 0);
    const bool CVB = (MODE == 0 || MODE == 1);
    const int t = threadIdx.x;

    int nh = 0, m0 = 0, KT = 128, RS = 128;
    const float* Ag = Aext;
    const float* Bg = Bext;
    if (MODE == 0) { m0 = blockIdx.x * 128; }
    if (MODE == 1) { m0 = blockIdx.x * 128; Ag = g_he0; }
    if (MODE == 2) { nh = blockIdx.x >> 1; m0 = (blockIdx.x & 1) * 128; KT = 512;
                     Bg = g_xh + (size_t)nh * 512 * 128; }
    if (MODE == 3) { nh = blockIdx.x >> 2; m0 = (blockIdx.x & 3) * 128; KT = 256; RS = 256;
                     Ag = g_att2 + (size_t)nh * 512 * 256;
                     Bg = g_he + (size_t)nh * 256 * 128; }

    if (MODE == 2) {
        sS[t]       = f2tf(g_s[(size_t)nh * 512 + t]);
        sS[t + 256] = f2tf(g_s[(size_t)nh * 512 + t + 256]);
    } else if (MODE == 0 || MODE == 1) {
        if (t < 128) {
            sS[t]  = __float_as_uint(bias[t]);
            sW2[t] = __float_as_uint(wA[t]);
            if (MODE == 0) sW4[t] = __float_as_uint(wB[t]);
        }
    }
    __syncthreads();   // sS visible before cross-thread reads in storeT

    const int lane = t & 31, wid = t >> 5;
    const int gq = lane >> 2, cq = lane & 3;
    const int wm = (wid & 1) * 64, wn = (wid >> 1) * 32;

    float acc[4][4][4];
    #pragma unroll
    for (int a = 0; a < 4; a++)
        #pragma unroll
        for (int b = 0; b < 4; b++)
            #pragma unroll
            for (int c = 0; c < 4; c++) acc[a][b][c] = 0.0f;

    float4 pa0, pa1, pb0, pb1;
    unsigned pmb = 0;

    auto loadT = [&](int k0) {
        {
            int i0 = t, i1 = t + 256;
            pb0 = *(const float4*)(Bg + (size_t)(k0 + (i0 >> 5)) * 128 + (i0 & 31) * 4);
            pb1 = *(const float4*)(Bg + (size_t)(k0 + (i1 >> 5)) * 128 + (i1 & 31) * 4);
        }
        if (MODE == 2) {
            pmb = g_mbits[((nh >> 3) * 256 + m0 + (t & 127)) * 16 + (k0 >> 5)];
        } else {
            pa0 = *(const float4*)(Ag + (size_t)(m0 + (t >> 2)) * RS + k0 + (t & 3) * 4);
            int i1 = t + 256;
            pa1 = *(const float4*)(Ag + (size_t)(m0 + (i1 >> 2)) * RS + k0 + (i1 & 3) * 4);
        }
    };
    auto storeT = [&](int bf, int k0) {
        #pragma unroll
        for (int rr = 0; rr < 2; rr++) {
            int i = t + 256 * rr;
            float4 v = rr ? pb1 : pb0;
            unsigned* d = &Bs[bf * BSZ + (i >> 5) * SB + (i & 31) * 4];
            if (CVB) { d[0]=f2tf(v.x); d[1]=f2tf(v.y); d[2]=f2tf(v.z); d[3]=f2tf(v.w); }
            else     { d[0]=__float_as_uint(v.x); d[1]=__float_as_uint(v.y);
                       d[2]=__float_as_uint(v.z); d[3]=__float_as_uint(v.w); }
        }
        if (MODE == 2) {
            int p = t & 127, kh = (t >> 7) * 8, sh = (k0 & 16);
            int m16 = p >> 4, r8 = (p >> 3) & 1, g8 = p & 7, rot = g8 & 3;
            int ksc = kh >> 3;
            unsigned* d = &As[bf * ASZ + (m16 * 2 + ksc) * 136 + g8 * 16 + r8];
            #pragma unroll
            for (int j = 0; j < 8; j++) {
                unsigned val = ((pmb >> (sh + kh + j)) & 1u) ? sS[k0 + kh + j]
                                                             : 0x3e000000u; // tf32(0.125)
                d[(((j & 3) + rot) & 3) * 4 + 2 * (j >> 2)] = val;
            }
        } else {
            #pragma unroll
            for (int rr = 0; rr < 2; rr++) {
                int i = t + 256 * rr;
                float4 v = rr ? pa1 : pa0;
                int row = i >> 2, k0c = (i & 3) * 4;
                int m16 = row >> 4, r8 = (row >> 3) & 1, g8 = row & 7, rot = g8 & 3;
                int ksc = k0c >> 3, kh2 = (k0c >> 2) & 1;
                unsigned* d = &As[bf * ASZ + (m16 * 2 + ksc) * 136 + g8 * 16 + r8 + 2 * kh2];
                unsigned w0, w1, w2, w3;
                if (CVA) { w0=f2tf(v.x); w1=f2tf(v.y); w2=f2tf(v.z); w3=f2tf(v.w); }
                else     { w0=__float_as_uint(v.x); w1=__float_as_uint(v.y);
                           w2=__float_as_uint(v.z); w3=__float_as_uint(v.w); }
                d[((0 + rot) & 3) * 4] = w0;
                d[((1 + rot) & 3) * 4] = w1;
                d[((2 + rot) & 3) * 4] = w2;
                d[((3 + rot) & 3) * 4] = w3;
            }
        }
    };

    loadT(0);
    storeT(0, 0);
    __syncthreads();

    const int slotA = (gq * 4 + ((cq + gq) & 3)) * 4;
    const int m16w = wm >> 4;   // 0 or 4

    int bf = 0;
    for (int k0 = 0; k0 < KT; k0 += 16) {
        int nk = k0 + 16;
        if (nk < KT) loadT(nk);
        const unsigned* Ab = &As[bf * ASZ];
        const unsigned* Bb = &Bs[bf * BSZ];
        #pragma unroll
        for (int ksc = 0; ksc < 2; ksc++) {
            unsigned a[4][4], b[4][2];
            #pragma unroll
            for (int mi = 0; mi < 4; mi++) {
                uint4 v = *(const uint4*)&Ab[((m16w + mi) * 2 + ksc) * 136 + slotA];
                a[mi][0] = v.x; a[mi][1] = v.y; a[mi][2] = v.z; a[mi][3] = v.w;
            }
            #pragma unroll
            for (int ni = 0; ni < 4; ni++) {
                int o = (ksc * 8 + cq) * SB + wn + ni * 8 + gq;
                b[ni][0] = Bb[o];
                b[ni][1] = Bb[o + 4 * SB];
            }
            #pragma unroll
            for (int mi = 0; mi < 4; mi++)
                #pragma unroll
                for (int ni = 0; ni < 4; ni++)
                    mma8(acc[mi][ni], a[mi], b[ni]);
        }
        if (nk < KT) {
            storeT(bf ^ 1, nk);
            __syncthreads();
        }
        bf ^= 1;
    }

    // ---------------- epilogue ----------------
    float dA[8], dB[8];
    #pragma unroll
    for (int i = 0; i < 8; i++) { dA[i] = 0.0f; dB[i] = 0.0f; }

    #pragma unroll
    for (int mi = 0; mi < 4; mi++) {
        #pragma unroll
        for (int half = 0; half < 2; half++) {
            int rl = wm + mi * 16 + gq + half * 8;   // 0..127
            int di = mi * 2 + half;
            size_t base = 0;
            int noe = 0;
            if (MODE == 0) {
                int rowg = m0 + rl;
                int n = rowg >> 12, rem = rowg & 4095;
                int l = rem >> 3, h = rem & 7;
                base = ((size_t)((n * 8 + h) * 512 + l)) * 128;
            } else if (MODE == 1) {
                base = (size_t)(m0 + rl) * 128;
            } else if (MODE == 2) {
                base = ((size_t)(nh * 256 + m0 + rl)) * 128;
            } else {
                int l = m0 + rl;
                int n = nh >> 3, h = nh & 7;
                noe = g_noedge[n * CL + l];
                base = ((size_t)(n * CL + l)) * 1024 + h * 128;
            }
            #pragma unroll
            for (int ni = 0; ni < 4; ni++) {
                int col = wn + ni * 8 + 2 * cq;
                float v0 = acc[mi][ni][half * 2 + 0];
                float v1 = acc[mi][ni][half * 2 + 1];
                if (MODE == 0 || MODE == 1) {
                    v0 += __uint_as_float(sS[col]);
                    v1 += __uint_as_float(sS[col + 1]);
                    float g0 = gelu1(v0), g1 = gelu1(v1);
                    dA[di] += g0 * __uint_as_float(sW2[col]) + g1 * __uint_as_float(sW2[col + 1]);
                    if (MODE == 0)
                        dB[di] += g0 * __uint_as_float(sW4[col]) + g1 * __uint_as_float(sW4[col + 1]);
                    float* dst = (MODE == 0) ? g_xh : g_he;
                    *(float2*)(dst + base + col) =
                        make_float2(__uint_as_float(f2tf(v0)), __uint_as_float(f2tf(v1)));
                } else if (MODE == 2) {
                    *(float2*)(g_he0 + base + col) =
                        make_float2(__uint_as_float(f2tf(gelu1(v0))),
                                    __uint_as_float(f2tf(gelu1(v1))));
                } else {
                    float2 r;
                    if (noe) r = *(const float2*)(xin + base + col);
                    else     r = make_float2(gelu1(v0), gelu1(v1));
                    *(float2*)(outx + base + col) = r;
                }
            }
        }
    }

    if (MODE == 0 || MODE == 1) {
        #pragma unroll
        for (int i = 0; i < 8; i++) {
            dA[i] += __shfl_xor_sync(0xffffffffu, dA[i], 1);
            dA[i] += __shfl_xor_sync(0xffffffffu, dA[i], 2);
            if (MODE == 0) {
                dB[i] += __shfl_xor_sync(0xffffffffu, dB[i], 1);
                dB[i] += __shfl_xor_sync(0xffffffffu, dB[i], 2);
            }
        }
        if (cq == 0) {
            #pragma unroll
            for (int i = 0; i < 8; i++) {
                int rl = wm + (i >> 1) * 16 + gq + 8 * (i & 1);
                sD1[(wid >> 1) * 128 + rl] = dA[i];
                if (MODE == 0) sD2[(wid >> 1) * 128 + rl] = dB[i];
            }
        }
        __syncthreads();
        if (t < 128) {   // warps 0..3 fully active
            float d1 = sD1[t] + sD1[128 + t] + sD1[256 + t] + sD1[384 + t];
            if (MODE == 1) {
                g_ae[m0 + t] = d1;
            } else {
                float d2 = sD2[t] + sD2[128 + t] + sD2[256 + t] + sD2[384 + t];
                int rowg = m0 + t;
                int n = rowg >> 12, rem = rowg & 4095;
                int l = rem >> 3, h = rem & 7;
                g_an[(size_t)(n * 8 + h) * 512 + l] = d2;
                float mx = d1;
                mx = fmaxf(mx, __shfl_xor_sync(0xffffffffu, mx, 1));
                mx = fmaxf(mx, __shfl_xor_sync(0xffffffffu, mx, 2));
                mx = fmaxf(mx, __shfl_xor_sync(0xffffffffu, mx, 4));
                float e = __expf(d1 - mx);
                float se = e;
                se += __shfl_xor_sync(0xffffffffu, se, 1);
                se += __shfl_xor_sync(0xffffffffu, se, 2);
                se += __shfl_xor_sync(0xffffffffu, se, 4);
                g_s[(size_t)(n * 8 + h) * 512 + l] = e / se;
            }
        }
    }
}

extern "C" void kernel_launch(void* const* d_in, const int* in_sizes, int n_in,
                              void* d_out, int out_size) {
    const float* x   = (const float*)d_in[0];
    const float* adj = (const float*)d_in[1];
    const float* W1  = (const float*)d_in[2];
    const float* b1  = (const float*)d_in[3];
    const float* W2  = (const float*)d_in[4];
    const float* W3  = (const float*)d_in[6];
    const float* b3  = (const float*)d_in[7];
    const float* W4  = (const float*)d_in[8];
    float* out = (float*)d_out;
    (void)in_sizes; (void)n_in; (void)out_size;

    cudaFuncSetAttribute(mma_k<0>, cudaFuncAttributeMaxDynamicSharedMemorySize, SMEM_BYTES);
    cudaFuncSetAttribute(mma_k<1>, cudaFuncAttributeMaxDynamicSharedMemorySize, SMEM_BYTES);
    cudaFuncSetAttribute(mma_k<2>, cudaFuncAttributeMaxDynamicSharedMemorySize, SMEM_BYTES);
    cudaFuncSetAttribute(mma_k<3>, cudaFuncAttributeMaxDynamicSharedMemorySize, SMEM_BYTES);

    mbits_k<<<dim3(CL / 32, CN), 256>>>(adj);
    mma_k<0><<<(CN * CL * CH) / 128, 256, SMEM_BYTES>>>(x, W1, b1, W2, W4 + CE, nullptr, nullptr);
    mma_k<2><<<CN * CH * 2, 256, SMEM_BYTES>>>(nullptr, nullptr, nullptr, nullptr, nullptr, nullptr, nullptr);
    mma_k<1><<<(CN * CH * CP) / 128, 256, SMEM_BYTES>>>(nullptr, W3, b3, W4, nullptr, nullptr, nullptr);
    att2fill_k<<<dim3(CL, CN), 256>>>(adj);
    mma_k<3><<<CN * CH * 4, 256, SMEM_BYTES>>>(nullptr, nullptr, nullptr, nullptr, nullptr, x, out);
}

// round 13
// speedup vs baseline: 1.4622x; 1.0537x over previous
#include <cuda_runtime.h>
#include <math.h>
#include <stdint.h>

// Problem constants
static const int CN = 32;    // batch
static const int CL = 512;   // nodes
static const int CP = 256;   // hyperedges
static const int CH = 8;     // heads
static const int CE = 128;   // emb per head
static const int CD = 1024;  // d_model

// -------- scratch (device globals; no allocation allowed) --------
// g_xh, g_he0, g_he, g_att2, g_w1t, g_w3t hold tf32-rounded bit patterns.
__device__ __align__(16) float    g_xh  [CN*CH*CL*CE];
__device__ __align__(16) float    g_he0 [CN*CH*CP*CE];
__device__ __align__(16) float    g_he  [CN*CH*CP*CE];
__device__ __align__(16) float    g_att2[CN*CH*CL*CP];
__device__ __align__(16) float    g_w1t [CE*CE];
__device__ __align__(16) float    g_w3t [CE*CE];
__device__ __align__(16) unsigned g_mbits[CN*CP*16];    // [n][p][l/32]
__device__ int   g_noedge[CN*CL];
__device__ float g_an[CN*CH*CL];
__device__ float g_s [CN*CH*CL];
__device__ float g_ae[CN*CH*CP];

__device__ __forceinline__ float gelu1(float x) {
    return 0.5f * x * (1.0f + erff(x * 0.7071067811865476f));
}
__device__ __forceinline__ unsigned f2tf(float x) {
    unsigned r; asm("cvt.rna.tf32.f32 %0, %1;" : "=r"(r) : "f"(x)); return r;
}
__device__ __forceinline__ void mma8(float* c, const unsigned* a, const unsigned* b) {
    asm volatile("mma.sync.aligned.m16n8k8.row.col.f32.tf32.tf32.f32 "
                 "{%0,%1,%2,%3},{%4,%5,%6,%7},{%8,%9},{%0,%1,%2,%3};"
                 : "+f"(c[0]), "+f"(c[1]), "+f"(c[2]), "+f"(c[3])
                 : "r"(a[0]), "r"(a[1]), "r"(a[2]), "r"(a[3]), "r"(b[0]), "r"(b[1]));
}
__device__ __forceinline__ void cpa16(void* dst, const void* src) {
    unsigned d = (unsigned)__cvta_generic_to_shared(dst);
    asm volatile("cp.async.cg.shared.global [%0], [%1], 16;" :: "r"(d), "l"(src));
}
#define CPA_COMMIT() asm volatile("cp.async.commit_group;" ::: "memory")
#define CPA_WAIT2()  asm volatile("cp.async.wait_group 2;" ::: "memory")

// -------- W pre-convert to tf32 bits --------
__global__ void __launch_bounds__(256) wcvt_k(const float* __restrict__ W1,
                                              const float* __restrict__ W3) {
    int i = blockIdx.x * 256 + threadIdx.x;
    g_w1t[i] = __uint_as_float(f2tf(W1[i]));
    g_w3t[i] = __uint_as_float(f2tf(W3[i]));
}

// -------- mask bit-pack --------
__global__ void __launch_bounds__(256) mbits_k(const float* __restrict__ adj) {
    __shared__ float sm[32 * 257];
    int l0 = blockIdx.x * 32, n = blockIdx.y;
    int t = threadIdx.x;   // = p
    for (int r = 0; r < 32; ++r)
        sm[r * 257 + t] = adj[((size_t)(n * CL) + l0 + r) * CP + t];
    __syncthreads();
    unsigned w = 0;
    #pragma unroll
    for (int j = 0; j < 32; ++j)
        if (sm[j * 257 + t] != 0.0f) w |= (1u << j);
    g_mbits[(n * CP + t) * 16 + (l0 >> 5)] = w;
}

// -------- node-attention fill (tf32 bits) + noedge flag --------
__global__ void __launch_bounds__(256) att2fill_k(const float* __restrict__ adj) {
    __shared__ float an_s[8];
    int l = blockIdx.x, n = blockIdx.y;
    int p = threadIdx.x;
    float mv = adj[((size_t)(n * CL) + l) * CP + p];
    int valid = (mv != 0.0f);
    if (p < 8) an_s[p] = g_an[(size_t)(n * 8 + p) * 512 + l];
    __syncthreads();
    unsigned sm[8];
    if (valid) {
        float u[8]; float mx = -1e30f;
        #pragma unroll
        for (int h = 0; h < 8; h++) {
            u[h] = an_s[h] + g_ae[(size_t)(n * 8 + h) * 256 + p];
            mx = fmaxf(mx, u[h]);
        }
        float s = 0.0f;
        #pragma unroll
        for (int h = 0; h < 8; h++) { u[h] = __expf(u[h] - mx); s += u[h]; }
        float inv = 1.0f / s;
        #pragma unroll
        for (int h = 0; h < 8; h++) sm[h] = f2tf(u[h] * inv);
    } else {
        #pragma unroll
        for (int h = 0; h < 8; h++) sm[h] = 0x3e000000u;   // tf32(0.125)
    }
    #pragma unroll
    for (int h = 0; h < 8; h++)
        g_att2[(((size_t)(n * 8 + h)) * 512 + l) * 256 + p] = __uint_as_float(sm[h]);
    int any = __syncthreads_or(valid);
    if (p == 0) g_noedge[n * CL + l] = !any;
}

// -------- unified tf32 MMA kernel: 4-stage cp.async pipeline --------
// MODE 0: A=x (cvt at frag), B=g_w1t, +b1, PERM -> g_xh(tf32); fused dots+softmax
// MODE 1: A=g_he0, B=g_w3t, +b3 -> g_he(tf32); fused gelu-dot -> g_ae
// MODE 2: per (n,h)x2: A=att1 synth from mbits/g_s, B=g_xh, gelu -> g_he0(tf32)
// MODE 3: per (n,h)x4: A=g_att2, B=g_he, gelu/scatter -> out (fp32)
static const int NSTG = 4;
static const int SA   = 20;          // A row stride (u32): 16 k + 4 pad
static const int ASZ  = 128 * SA;    // 2560 words
static const int SB   = 136;         // B row stride (u32)
static const int BSZ  = 16 * SB;     // 2176 words
static const int SMEM_WORDS = NSTG * (ASZ + BSZ) + 512 + 128 + 128 + 512 + 512;
static const int SMEM_BYTES = SMEM_WORDS * 4;   // 82944

template<int MODE>
__global__ void __launch_bounds__(256, 2) mma_k(const float* __restrict__ Aext,
                                                const float* __restrict__ bias,
                                                const float* __restrict__ wA,
                                                const float* __restrict__ wB,
                                                const float* __restrict__ xin,
                                                float* __restrict__ outx) {
    extern __shared__ unsigned dyns[];
    unsigned* As  = dyns;                     // NSTG*ASZ
    unsigned* Bs  = As + NSTG * ASZ;          // NSTG*BSZ
    unsigned* sS  = Bs + NSTG * BSZ;          // 512
    unsigned* sW2 = sS + 512;                 // 128
    unsigned* sW4 = sW2 + 128;                // 128
    float* sD1 = (float*)(sW4 + 128);         // 512
    float* sD2 = sD1 + 512;                   // 512

    const int t = threadIdx.x;

    int nh = 0, m0 = 0, KT = 128, RS = 128;
    const float* Ag = Aext;
    const float* Bg = nullptr;
    if (MODE == 0) { m0 = blockIdx.x * 128; Bg = g_w1t; }
    if (MODE == 1) { m0 = blockIdx.x * 128; Ag = g_he0; Bg = g_w3t; }
    if (MODE == 2) { nh = blockIdx.x >> 1; m0 = (blockIdx.x & 1) * 128; KT = 512;
                     Bg = g_xh + (size_t)nh * 512 * 128; }
    if (MODE == 3) { nh = blockIdx.x >> 2; m0 = (blockIdx.x & 3) * 128; KT = 256; RS = 256;
                     Ag = g_att2 + (size_t)nh * 512 * 256;
                     Bg = g_he + (size_t)nh * 256 * 128; }
    const int NIT = KT / 16;

    if (MODE == 2) {
        sS[t]       = f2tf(g_s[(size_t)nh * 512 + t]);
        sS[t + 256] = f2tf(g_s[(size_t)nh * 512 + t + 256]);
    } else if (MODE == 0 || MODE == 1) {
        if (t < 128) {
            sS[t]  = __float_as_uint(bias[t]);
            sW2[t] = __float_as_uint(wA[t]);
            if (MODE == 0) sW4[t] = __float_as_uint(wB[t]);
        }
    }
    __syncthreads();   // sS visible before synth reads it

    const int lane = t & 31, wid = t >> 5;
    const int gq = lane >> 2, cq = lane & 3;
    const int wm = (wid & 1) * 64, wn = (wid >> 1) * 32;

    float acc[4][4][4];
    #pragma unroll
    for (int a = 0; a < 4; a++)
        #pragma unroll
        for (int b = 0; b < 4; b++)
            #pragma unroll
            for (int c = 0; c < 4; c++) acc[a][b][c] = 0.0f;

    auto issue = [&](int it) {
        if (it < NIT) {
            int k0 = it * 16, st = it & (NSTG - 1);
            #pragma unroll
            for (int rr = 0; rr < 2; rr++) {
                int i = t + 256 * rr;
                cpa16(&Bs[st * BSZ + (i >> 5) * SB + (i & 31) * 4],
                      Bg + (size_t)(k0 + (i >> 5)) * 128 + (i & 31) * 4);
            }
            if (MODE != 2) {
                #pragma unroll
                for (int rr = 0; rr < 2; rr++) {
                    int u = t + 256 * rr;
                    int row = u >> 2, seg = u & 3;
                    cpa16(&As[st * ASZ + row * SA + seg * 4],
                          Ag + (size_t)(m0 + row) * RS + k0 + seg * 4);
                }
            }
        }
        CPA_COMMIT();
    };
    auto synth = [&](int it) {   // MODE 2 only
        if (it < NIT) {
            int k0 = it * 16, st = it & (NSTG - 1);
            int p = t & 127, kh = (t >> 7) * 8, sh = k0 & 16;
            unsigned pmb = g_mbits[((nh >> 3) * 256 + m0 + p) * 16 + (k0 >> 5)];
            unsigned* d = &As[st * ASZ + p * SA + kh];
            #pragma unroll
            for (int j = 0; j < 8; j++)
                d[j] = ((pmb >> (sh + kh + j)) & 1u) ? sS[k0 + kh + j] : 0x3e000000u;
        }
    };

    // prologue: stages 0..NSTG-2
    #pragma unroll
    for (int s = 0; s < NSTG - 1; s++) {
        issue(s);
        if (MODE == 2) synth(s);
    }

    for (int it = 0; it < NIT; ++it) {
        CPA_WAIT2();
        __syncthreads();
        const unsigned* Ab = &As[(it & (NSTG - 1)) * ASZ];
        const unsigned* Bb = &Bs[(it & (NSTG - 1)) * BSZ];
        #pragma unroll
        for (int ksc = 0; ksc < 2; ksc++) {
            int ks = ksc * 8;
            unsigned a[4][4], b[4][2];
            #pragma unroll
            for (int mi = 0; mi < 4; mi++) {
                int r0 = (wm + mi * 16 + gq) * SA + ks + cq;
                a[mi][0] = Ab[r0];
                a[mi][1] = Ab[r0 + 8 * SA];
                a[mi][2] = Ab[r0 + 4];
                a[mi][3] = Ab[r0 + 8 * SA + 4];
                if (MODE == 0) {
                    a[mi][0] = f2tf(__uint_as_float(a[mi][0]));
                    a[mi][1] = f2tf(__uint_as_float(a[mi][1]));
                    a[mi][2] = f2tf(__uint_as_float(a[mi][2]));
                    a[mi][3] = f2tf(__uint_as_float(a[mi][3]));
                }
            }
            #pragma unroll
            for (int ni = 0; ni < 4; ni++) {
                int o = (ks + cq) * SB + wn + ni * 8 + gq;
                b[ni][0] = Bb[o];
                b[ni][1] = Bb[o + 4 * SB];
            }
            #pragma unroll
            for (int mi = 0; mi < 4; mi++)
                #pragma unroll
                for (int ni = 0; ni < 4; ni++)
                    mma8(acc[mi][ni], a[mi], b[ni]);
        }
        issue(it + NSTG - 1);
        if (MODE == 2) synth(it + NSTG - 1);
    }

    // ---------------- epilogue ----------------
    float dA[8], dB[8];
    #pragma unroll
    for (int i = 0; i < 8; i++) { dA[i] = 0.0f; dB[i] = 0.0f; }

    #pragma unroll
    for (int mi = 0; mi < 4; mi++) {
        #pragma unroll
        for (int half = 0; half < 2; half++) {
            int rl = wm + mi * 16 + gq + half * 8;   // 0..127
            int di = mi * 2 + half;
            size_t base = 0;
            int noe = 0;
            if (MODE == 0) {
                int rowg = m0 + rl;
                int n = rowg >> 12, rem = rowg & 4095;
                int l = rem >> 3, h = rem & 7;
                base = ((size_t)((n * 8 + h) * 512 + l)) * 128;
            } else if (MODE == 1) {
                base = (size_t)(m0 + rl) * 128;
            } else if (MODE == 2) {
                base = ((size_t)(nh * 256 + m0 + rl)) * 128;
            } else {
                int l = m0 + rl;
                int n = nh >> 3, h = nh & 7;
                noe = g_noedge[n * CL + l];
                base = ((size_t)(n * CL + l)) * 1024 + h * 128;
            }
            #pragma unroll
            for (int ni = 0; ni < 4; ni++) {
                int col = wn + ni * 8 + 2 * cq;
                float v0 = acc[mi][ni][half * 2 + 0];
                float v1 = acc[mi][ni][half * 2 + 1];
                if (MODE == 0 || MODE == 1) {
                    v0 += __uint_as_float(sS[col]);
                    v1 += __uint_as_float(sS[col + 1]);
                    float g0 = gelu1(v0), g1 = gelu1(v1);
                    dA[di] += g0 * __uint_as_float(sW2[col]) + g1 * __uint_as_float(sW2[col + 1]);
                    if (MODE == 0)
                        dB[di] += g0 * __uint_as_float(sW4[col]) + g1 * __uint_as_float(sW4[col + 1]);
                    float* dst = (MODE == 0) ? g_xh : g_he;
                    *(float2*)(dst + base + col) =
                        make_float2(__uint_as_float(f2tf(v0)), __uint_as_float(f2tf(v1)));
                } else if (MODE == 2) {
                    *(float2*)(g_he0 + base + col) =
                        make_float2(__uint_as_float(f2tf(gelu1(v0))),
                                    __uint_as_float(f2tf(gelu1(v1))));
                } else {
                    float2 r;
                    if (noe) r = *(const float2*)(xin + base + col);
                    else     r = make_float2(gelu1(v0), gelu1(v1));
                    *(float2*)(outx + base + col) = r;
                }
            }
        }
    }

    if (MODE == 0 || MODE == 1) {
        #pragma unroll
        for (int i = 0; i < 8; i++) {
            dA[i] += __shfl_xor_sync(0xffffffffu, dA[i], 1);
            dA[i] += __shfl_xor_sync(0xffffffffu, dA[i], 2);
            if (MODE == 0) {
                dB[i] += __shfl_xor_sync(0xffffffffu, dB[i], 1);
                dB[i] += __shfl_xor_sync(0xffffffffu, dB[i], 2);
            }
        }
        if (cq == 0) {
            #pragma unroll
            for (int i = 0; i < 8; i++) {
                int rl = wm + (i >> 1) * 16 + gq + 8 * (i & 1);
                sD1[(wid >> 1) * 128 + rl] = dA[i];
                if (MODE == 0) sD2[(wid >> 1) * 128 + rl] = dB[i];
            }
        }
        __syncthreads();
        if (t < 128) {   // warps 0..3 fully active
            float d1 = sD1[t] + sD1[128 + t] + sD1[256 + t] + sD1[384 + t];
            if (MODE == 1) {
                g_ae[m0 + t] = d1;
            } else {
                float d2 = sD2[t] + sD2[128 + t] + sD2[256 + t] + sD2[384 + t];
                int rowg = m0 + t;
                int n = rowg >> 12, rem = rowg & 4095;
                int l = rem >> 3, h = rem & 7;
                g_an[(size_t)(n * 8 + h) * 512 + l] = d2;
                float mx = d1;
                mx = fmaxf(mx, __shfl_xor_sync(0xffffffffu, mx, 1));
                mx = fmaxf(mx, __shfl_xor_sync(0xffffffffu, mx, 2));
                mx = fmaxf(mx, __shfl_xor_sync(0xffffffffu, mx, 4));
                float e = __expf(d1 - mx);
                float se = e;
                se += __shfl_xor_sync(0xffffffffu, se, 1);
                se += __shfl_xor_sync(0xffffffffu, se, 2);
                se += __shfl_xor_sync(0xffffffffu, se, 4);
                g_s[(size_t)(n * 8 + h) * 512 + l] = e / se;
            }
        }
    }
}

extern "C" void kernel_launch(void* const* d_in, const int* in_sizes, int n_in,
                              void* d_out, int out_size) {
    const float* x   = (const float*)d_in[0];
    const float* adj = (const float*)d_in[1];
    const float* W1  = (const float*)d_in[2];
    const float* b1  = (const float*)d_in[3];
    const float* W2  = (const float*)d_in[4];
    const float* W3  = (const float*)d_in[6];
    const float* b3  = (const float*)d_in[7];
    const float* W4  = (const float*)d_in[8];
    float* out = (float*)d_out;
    (void)in_sizes; (void)n_in; (void)out_size;

    cudaFuncSetAttribute(mma_k<0>, cudaFuncAttributeMaxDynamicSharedMemorySize, SMEM_BYTES);
    cudaFuncSetAttribute(mma_k<1>, cudaFuncAttributeMaxDynamicSharedMemorySize, SMEM_BYTES);
    cudaFuncSetAttribute(mma_k<2>, cudaFuncAttributeMaxDynamicSharedMemorySize, SMEM_BYTES);
    cudaFuncSetAttribute(mma_k<3>, cudaFuncAttributeMaxDynamicSharedMemorySize, SMEM_BYTES);

    wcvt_k<<<64, 256>>>(W1, W3);
    mbits_k<<<dim3(CL / 32, CN), 256>>>(adj);
    mma_k<0><<<(CN * CL * CH) / 128, 256, SMEM_BYTES>>>(x, b1, W2, W4 + CE, nullptr, nullptr);
    mma_k<2><<<CN * CH * 2, 256, SMEM_BYTES>>>(nullptr, nullptr, nullptr, nullptr, nullptr, nullptr);
    mma_k<1><<<(CN * CH * CP) / 128, 256, SMEM_BYTES>>>(nullptr, b3, W4, nullptr, nullptr, nullptr);
    att2fill_k<<<dim3(CL, CN), 256>>>(adj);
    mma_k<3><<<CN * CH * 4, 256, SMEM_BYTES>>>(nullptr, nullptr, nullptr, nullptr, x, out);
}

// round 14
// speedup vs baseline: 1.5541x; 1.0629x over previous
#include <cuda_runtime.h>
#include <math.h>
#include <stdint.h>

// Problem constants
static const int CN = 32;    // batch
static const int CL = 512;   // nodes
static const int CP = 256;   // hyperedges
static const int CH = 8;     // heads
static const int CE = 128;   // emb per head
static const int CD = 1024;  // d_model

// -------- scratch (device globals; no allocation allowed) --------
// g_xh, g_he0, g_he, g_att2, g_w1t, g_w3t hold tf32-rounded bit patterns.
__device__ __align__(16) float    g_xh  [CN*CH*CL*CE];
__device__ __align__(16) float    g_he0 [CN*CH*CP*CE];
__device__ __align__(16) float    g_he  [CN*CH*CP*CE];
__device__ __align__(16) float    g_att2[CN*CH*CL*CP];
__device__ __align__(16) float    g_w1t [CE*CE];
__device__ __align__(16) float    g_w3t [CE*CE];
__device__ __align__(16) unsigned g_mbits[CN*CP*16];    // [n][p][l/32]
__device__ int   g_noedge[CN*CL];
__device__ float g_an[CN*CH*CL];
__device__ float g_s [CN*CH*CL];
__device__ float g_ae[CN*CH*CP];

__device__ __forceinline__ float gelu1(float x) {
    return 0.5f * x * (1.0f + erff(x * 0.7071067811865476f));
}
__device__ __forceinline__ unsigned f2tf(float x) {
    unsigned r; asm("cvt.rna.tf32.f32 %0, %1;" : "=r"(r) : "f"(x)); return r;
}
__device__ __forceinline__ void mma8(float* c, const unsigned* a, const unsigned* b) {
    asm volatile("mma.sync.aligned.m16n8k8.row.col.f32.tf32.tf32.f32 "
                 "{%0,%1,%2,%3},{%4,%5,%6,%7},{%8,%9},{%0,%1,%2,%3};"
                 : "+f"(c[0]), "+f"(c[1]), "+f"(c[2]), "+f"(c[3])
                 : "r"(a[0]), "r"(a[1]), "r"(a[2]), "r"(a[3]), "r"(b[0]), "r"(b[1]));
}
__device__ __forceinline__ void cpa16(void* dst, const void* src) {
    unsigned d = (unsigned)__cvta_generic_to_shared(dst);
    asm volatile("cp.async.cg.shared.global [%0], [%1], 16;" :: "r"(d), "l"(src));
}
#define CPA_COMMIT() asm volatile("cp.async.commit_group;" ::: "memory")
#define CPA_WAIT2()  asm volatile("cp.async.wait_group 2;" ::: "memory")
#define CPA_WAIT0()  asm volatile("cp.async.wait_group 0;" ::: "memory")

// -------- W pre-convert to tf32 bits --------
__global__ void __launch_bounds__(256) wcvt_k(const float* __restrict__ W1,
                                              const float* __restrict__ W3) {
    int i = blockIdx.x * 256 + threadIdx.x;
    g_w1t[i] = __uint_as_float(f2tf(W1[i]));
    g_w3t[i] = __uint_as_float(f2tf(W3[i]));
}

// -------- mask bit-pack --------
__global__ void __launch_bounds__(256) mbits_k(const float* __restrict__ adj) {
    __shared__ float sm[32 * 257];
    int l0 = blockIdx.x * 32, n = blockIdx.y;
    int t = threadIdx.x;   // = p
    for (int r = 0; r < 32; ++r)
        sm[r * 257 + t] = adj[((size_t)(n * CL) + l0 + r) * CP + t];
    __syncthreads();
    unsigned w = 0;
    #pragma unroll
    for (int j = 0; j < 32; ++j)
        if (sm[j * 257 + t] != 0.0f) w |= (1u << j);
    g_mbits[(n * CP + t) * 16 + (l0 >> 5)] = w;
}

// -------- node-attention fill (tf32 bits) + noedge flag --------
__global__ void __launch_bounds__(256) att2fill_k(const float* __restrict__ adj) {
    __shared__ float an_s[8];
    int l = blockIdx.x, n = blockIdx.y;
    int p = threadIdx.x;
    float mv = adj[((size_t)(n * CL) + l) * CP + p];
    int valid = (mv != 0.0f);
    if (p < 8) an_s[p] = g_an[(size_t)(n * 8 + p) * 512 + l];
    __syncthreads();
    unsigned sm[8];
    if (valid) {
        float u[8]; float mx = -1e30f;
        #pragma unroll
        for (int h = 0; h < 8; h++) {
            u[h] = an_s[h] + g_ae[(size_t)(n * 8 + h) * 256 + p];
            mx = fmaxf(mx, u[h]);
        }
        float s = 0.0f;
        #pragma unroll
        for (int h = 0; h < 8; h++) { u[h] = __expf(u[h] - mx); s += u[h]; }
        float inv = 1.0f / s;
        #pragma unroll
        for (int h = 0; h < 8; h++) sm[h] = f2tf(u[h] * inv);
    } else {
        #pragma unroll
        for (int h = 0; h < 8; h++) sm[h] = 0x3e000000u;   // tf32(0.125)
    }
    #pragma unroll
    for (int h = 0; h < 8; h++)
        g_att2[(((size_t)(n * 8 + h)) * 512 + l) * 256 + p] = __uint_as_float(sm[h]);
    int any = __syncthreads_or(valid);
    if (p == 0) g_noedge[n * CL + l] = !any;
}

// -------- unified tf32 MMA kernel: 4-stage cp.async pipeline --------
// MODE 0: A=x (cvt at frag), B=g_w1t, +b1, PERM -> g_xh(tf32); fused dots+softmax
// MODE 1: A=g_he0, B=g_w3t, +b3 -> g_he(tf32); fused gelu-dot -> g_ae
// MODE 2: per (n,h)x2: A=att1 synth from smem mbits/g_s, B=g_xh, gelu -> g_he0(tf32)
// MODE 3: per (n,h)x4: A=g_att2, B=g_he, gelu/scatter -> out (fp32)
static const int NSTG = 4;
static const int SA   = 20;          // A row stride (u32): 16 k + 4 pad
static const int ASZ  = 128 * SA;    // 2560 words
static const int SB   = 136;         // B row stride (u32)
static const int BSZ  = 16 * SB;     // 2176 words
static const int MBW  = 128 * 20;    // mbits cache words (MODE 2 only)
static const int SMEM_WORDS  = NSTG * (ASZ + BSZ) + 512 + 128 + 128 + 512 + 512;
static const int SMEM_BYTES  = SMEM_WORDS * 4;              // 82944 (modes 0/1/3)
static const int SMEM2_BYTES = (SMEM_WORDS + MBW) * 4;      // 93184 (mode 2)

template<int MODE>
__global__ void __launch_bounds__(256, 2) mma_k(const float* __restrict__ Aext,
                                                const float* __restrict__ bias,
                                                const float* __restrict__ wA,
                                                const float* __restrict__ wB,
                                                const float* __restrict__ xin,
                                                float* __restrict__ outx) {
    extern __shared__ unsigned dyns[];
    unsigned* As  = dyns;                     // NSTG*ASZ
    unsigned* Bs  = As + NSTG * ASZ;          // NSTG*BSZ
    unsigned* sS  = Bs + NSTG * BSZ;          // 512
    unsigned* sW2 = sS + 512;                 // 128
    unsigned* sW4 = sW2 + 128;                // 128
    float* sD1 = (float*)(sW4 + 128);         // 512
    float* sD2 = sD1 + 512;                   // 512
    unsigned* sMb = (unsigned*)(sD2 + 512);   // MODE 2 only: 128*20

    const int t = threadIdx.x;

    int nh = 0, m0 = 0, KT = 128, RS = 128;
    const float* Ag = Aext;
    const float* Bg = nullptr;
    if (MODE == 0) { m0 = blockIdx.x * 128; Bg = g_w1t; }
    if (MODE == 1) { m0 = blockIdx.x * 128; Ag = g_he0; Bg = g_w3t; }
    if (MODE == 2) { nh = blockIdx.x >> 1; m0 = (blockIdx.x & 1) * 128; KT = 512;
                     Bg = g_xh + (size_t)nh * 512 * 128; }
    if (MODE == 3) { nh = blockIdx.x >> 2; m0 = (blockIdx.x & 3) * 128; KT = 256; RS = 256;
                     Ag = g_att2 + (size_t)nh * 512 * 256;
                     Bg = g_he + (size_t)nh * 256 * 128; }
    const int NIT = KT / 16;

    if (MODE == 2) {
        sS[t]       = f2tf(g_s[(size_t)nh * 512 + t]);
        sS[t + 256] = f2tf(g_s[(size_t)nh * 512 + t + 256]);
        // preload this CTA's mbits slice (128 rows x 16 u32) into smem, stride 20
        #pragma unroll
        for (int rr = 0; rr < 2; rr++) {
            int c = t + 256 * rr;            // 0..511 chunks of 16B
            int r = c >> 2, q = c & 3;
            cpa16(&sMb[r * 20 + q * 4],
                  g_mbits + ((size_t)((nh >> 3) * 256 + m0 + r)) * 16 + q * 4);
        }
        CPA_COMMIT();
        CPA_WAIT0();   // drained before the 3 pipeline groups are committed
    } else if (MODE == 0 || MODE == 1) {
        if (t < 128) {
            sS[t]  = __float_as_uint(bias[t]);
            sW2[t] = __float_as_uint(wA[t]);
            if (MODE == 0) sW4[t] = __float_as_uint(wB[t]);
        }
    }
    __syncthreads();   // sS + sMb visible before synth reads them

    const int lane = t & 31, wid = t >> 5;
    const int gq = lane >> 2, cq = lane & 3;
    const int wm = (wid & 1) * 64, wn = (wid >> 1) * 32;

    float acc[4][4][4];
    #pragma unroll
    for (int a = 0; a < 4; a++)
        #pragma unroll
        for (int b = 0; b < 4; b++)
            #pragma unroll
            for (int c = 0; c < 4; c++) acc[a][b][c] = 0.0f;

    auto issue = [&](int it) {
        if (it < NIT) {
            int k0 = it * 16, st = it & (NSTG - 1);
            #pragma unroll
            for (int rr = 0; rr < 2; rr++) {
                int i = t + 256 * rr;
                cpa16(&Bs[st * BSZ + (i >> 5) * SB + (i & 31) * 4],
                      Bg + (size_t)(k0 + (i >> 5)) * 128 + (i & 31) * 4);
            }
            if (MODE != 2) {
                #pragma unroll
                for (int rr = 0; rr < 2; rr++) {
                    int u = t + 256 * rr;
                    int row = u >> 2, seg = u & 3;
                    cpa16(&As[st * ASZ + row * SA + seg * 4],
                          Ag + (size_t)(m0 + row) * RS + k0 + seg * 4);
                }
            }
        }
        CPA_COMMIT();
    };
    auto synth = [&](int it) {   // MODE 2 only: all smem, fully vectorized
        if (it < NIT) {
            int k0 = it * 16, st = it & (NSTG - 1);
            int p = t & 127, kh = (t >> 7) * 8, sh = k0 & 16;
            unsigned pmb = sMb[p * 20 + (k0 >> 5)];
            uint4 s0 = *(const uint4*)&sS[k0 + kh];
            uint4 s1 = *(const uint4*)&sS[k0 + kh + 4];
            uint4 o0, o1;
            o0.x = ((pmb >> (sh + kh + 0)) & 1u) ? s0.x : 0x3e000000u;
            o0.y = ((pmb >> (sh + kh + 1)) & 1u) ? s0.y : 0x3e000000u;
            o0.z = ((pmb >> (sh + kh + 2)) & 1u) ? s0.z : 0x3e000000u;
            o0.w = ((pmb >> (sh + kh + 3)) & 1u) ? s0.w : 0x3e000000u;
            o1.x = ((pmb >> (sh + kh + 4)) & 1u) ? s1.x : 0x3e000000u;
            o1.y = ((pmb >> (sh + kh + 5)) & 1u) ? s1.y : 0x3e000000u;
            o1.z = ((pmb >> (sh + kh + 6)) & 1u) ? s1.z : 0x3e000000u;
            o1.w = ((pmb >> (sh + kh + 7)) & 1u) ? s1.w : 0x3e000000u;
            *(uint4*)&As[st * ASZ + p * SA + kh]     = o0;
            *(uint4*)&As[st * ASZ + p * SA + kh + 4] = o1;
        }
    };

    // prologue: stages 0..NSTG-2
    #pragma unroll
    for (int s = 0; s < NSTG - 1; s++) {
        issue(s);
        if (MODE == 2) synth(s);
    }

    for (int it = 0; it < NIT; ++it) {
        CPA_WAIT2();
        __syncthreads();
        const unsigned* Ab = &As[(it & (NSTG - 1)) * ASZ];
        const unsigned* Bb = &Bs[(it & (NSTG - 1)) * BSZ];
        #pragma unroll
        for (int ksc = 0; ksc < 2; ksc++) {
            int ks = ksc * 8;
            unsigned a[4][4], b[4][2];
            #pragma unroll
            for (int mi = 0; mi < 4; mi++) {
                int r0 = (wm + mi * 16 + gq) * SA + ks + cq;
                a[mi][0] = Ab[r0];
                a[mi][1] = Ab[r0 + 8 * SA];
                a[mi][2] = Ab[r0 + 4];
                a[mi][3] = Ab[r0 + 8 * SA + 4];
                if (MODE == 0) {
                    a[mi][0] = f2tf(__uint_as_float(a[mi][0]));
                    a[mi][1] = f2tf(__uint_as_float(a[mi][1]));
                    a[mi][2] = f2tf(__uint_as_float(a[mi][2]));
                    a[mi][3] = f2tf(__uint_as_float(a[mi][3]));
                }
            }
            #pragma unroll
            for (int ni = 0; ni < 4; ni++) {
                int o = (ks + cq) * SB + wn + ni * 8 + gq;
                b[ni][0] = Bb[o];
                b[ni][1] = Bb[o + 4 * SB];
            }
            #pragma unroll
            for (int mi = 0; mi < 4; mi++)
                #pragma unroll
                for (int ni = 0; ni < 4; ni++)
                    mma8(acc[mi][ni], a[mi], b[ni]);
        }
        issue(it + NSTG - 1);
        if (MODE == 2) synth(it + NSTG - 1);
    }

    // ---------------- epilogue ----------------
    float dA[8], dB[8];
    #pragma unroll
    for (int i = 0; i < 8; i++) { dA[i] = 0.0f; dB[i] = 0.0f; }

    #pragma unroll
    for (int mi = 0; mi < 4; mi++) {
        #pragma unroll
        for (int half = 0; half < 2; half++) {
            int rl = wm + mi * 16 + gq + half * 8;   // 0..127
            int di = mi * 2 + half;
            size_t base = 0;
            int noe = 0;
            if (MODE == 0) {
                int rowg = m0 + rl;
                int n = rowg >> 12, rem = rowg & 4095;
                int l = rem >> 3, h = rem & 7;
                base = ((size_t)((n * 8 + h) * 512 + l)) * 128;
            } else if (MODE == 1) {
                base = (size_t)(m0 + rl) * 128;
            } else if (MODE == 2) {
                base = ((size_t)(nh * 256 + m0 + rl)) * 128;
            } else {
                int l = m0 + rl;
                int n = nh >> 3, h = nh & 7;
                noe = g_noedge[n * CL + l];
                base = ((size_t)(n * CL + l)) * 1024 + h * 128;
            }
            #pragma unroll
            for (int ni = 0; ni < 4; ni++) {
                int col = wn + ni * 8 + 2 * cq;
                float v0 = acc[mi][ni][half * 2 + 0];
                float v1 = acc[mi][ni][half * 2 + 1];
                if (MODE == 0 || MODE == 1) {
                    v0 += __uint_as_float(sS[col]);
                    v1 += __uint_as_float(sS[col + 1]);
                    float g0 = gelu1(v0), g1 = gelu1(v1);
                    dA[di] += g0 * __uint_as_float(sW2[col]) + g1 * __uint_as_float(sW2[col + 1]);
                    if (MODE == 0)
                        dB[di] += g0 * __uint_as_float(sW4[col]) + g1 * __uint_as_float(sW4[col + 1]);
                    float* dst = (MODE == 0) ? g_xh : g_he;
                    *(float2*)(dst + base + col) =
                        make_float2(__uint_as_float(f2tf(v0)), __uint_as_float(f2tf(v1)));
                } else if (MODE == 2) {
                    *(float2*)(g_he0 + base + col) =
                        make_float2(__uint_as_float(f2tf(gelu1(v0))),
                                    __uint_as_float(f2tf(gelu1(v1))));
                } else {
                    float2 r;
                    if (noe) r = *(const float2*)(xin + base + col);
                    else     r = make_float2(gelu1(v0), gelu1(v1));
                    *(float2*)(outx + base + col) = r;
                }
            }
        }
    }

    if (MODE == 0 || MODE == 1) {
        #pragma unroll
        for (int i = 0; i < 8; i++) {
            dA[i] += __shfl_xor_sync(0xffffffffu, dA[i], 1);
            dA[i] += __shfl_xor_sync(0xffffffffu, dA[i], 2);
            if (MODE == 0) {
                dB[i] += __shfl_xor_sync(0xffffffffu, dB[i], 1);
                dB[i] += __shfl_xor_sync(0xffffffffu, dB[i], 2);
            }
        }
        if (cq == 0) {
            #pragma unroll
            for (int i = 0; i < 8; i++) {
                int rl = wm + (i >> 1) * 16 + gq + 8 * (i & 1);
                sD1[(wid >> 1) * 128 + rl] = dA[i];
                if (MODE == 0) sD2[(wid >> 1) * 128 + rl] = dB[i];
            }
        }
        __syncthreads();
        if (t < 128) {   // warps 0..3 fully active
            float d1 = sD1[t] + sD1[128 + t] + sD1[256 + t] + sD1[384 + t];
            if (MODE == 1) {
                g_ae[m0 + t] = d1;
            } else {
                float d2 = sD2[t] + sD2[128 + t] + sD2[256 + t] + sD2[384 + t];
                int rowg = m0 + t;
                int n = rowg >> 12, rem = rowg & 4095;
                int l = rem >> 3, h = rem & 7;
                g_an[(size_t)(n * 8 + h) * 512 + l] = d2;
                float mx = d1;
                mx = fmaxf(mx, __shfl_xor_sync(0xffffffffu, mx, 1));
                mx = fmaxf(mx, __shfl_xor_sync(0xffffffffu, mx, 2));
                mx = fmaxf(mx, __shfl_xor_sync(0xffffffffu, mx, 4));
                float e = __expf(d1 - mx);
                float se = e;
                se += __shfl_xor_sync(0xffffffffu, se, 1);
                se += __shfl_xor_sync(0xffffffffu, se, 2);
                se += __shfl_xor_sync(0xffffffffu, se, 4);
                g_s[(size_t)(n * 8 + h) * 512 + l] = e / se;
            }
        }
    }
}

extern "C" void kernel_launch(void* const* d_in, const int* in_sizes, int n_in,
                              void* d_out, int out_size) {
    const float* x   = (const float*)d_in[0];
    const float* adj = (const float*)d_in[1];
    const float* W1  = (const float*)d_in[2];
    const float* b1  = (const float*)d_in[3];
    const float* W2  = (const float*)d_in[4];
    const float* W3  = (const float*)d_in[6];
    const float* b3  = (const float*)d_in[7];
    const float* W4  = (const float*)d_in[8];
    float* out = (float*)d_out;
    (void)in_sizes; (void)n_in; (void)out_size;

    cudaFuncSetAttribute(mma_k<0>, cudaFuncAttributeMaxDynamicSharedMemorySize, SMEM_BYTES);
    cudaFuncSetAttribute(mma_k<1>, cudaFuncAttributeMaxDynamicSharedMemorySize, SMEM_BYTES);
    cudaFuncSetAttribute(mma_k<2>, cudaFuncAttributeMaxDynamicSharedMemorySize, SMEM2_BYTES);
    cudaFuncSetAttribute(mma_k<3>, cudaFuncAttributeMaxDynamicSharedMemorySize, SMEM_BYTES);

    wcvt_k<<<64, 256>>>(W1, W3);
    mbits_k<<<dim3(CL / 32, CN), 256>>>(adj);
    mma_k<0><<<(CN * CL * CH) / 128, 256, SMEM_BYTES>>>(x, b1, W2, W4 + CE, nullptr, nullptr);
    mma_k<2><<<CN * CH * 2, 256, SMEM2_BYTES>>>(nullptr, nullptr, nullptr, nullptr, nullptr, nullptr);
    mma_k<1><<<(CN * CH * CP) / 128, 256, SMEM_BYTES>>>(nullptr, b3, W4, nullptr, nullptr, nullptr);
    att2fill_k<<<dim3(CL, CN), 256>>>(adj);
    mma_k<3><<<CN * CH * 4, 256, SMEM_BYTES>>>(nullptr, nullptr, nullptr, nullptr, x, out);
}